// round 1
// baseline (speedup 1.0000x reference)
#include <cuda_runtime.h>
#include <math.h>

#define Hh 128
#define Ww 128
#define Cc 128
#define Nn (Hh*Ww)
#define Bb 2
#define NIMG 4          // img = tensor*2 + batch ; tensor 0 = u, 1 = v
#define KK9 9
#define OCH 18
#define NCHUNK 128

// -------- scratch (static device allocations; no runtime alloc allowed) ------
__device__ float g_xnhwc[NIMG][Nn][Cc];   // inputs transposed to NHWC
__device__ float g_off[NIMG][Nn][OCH];    // offset conv output, per-pixel 18 vals
__device__ float g_xd[NIMG][Nn][Cc];      // deformable conv outputs (NHWC)
__device__ float g_Wt[KK9][Cc][Cc];       // dcn_w transposed [kk][c][co]
__device__ float g_Wo[OCH][KK9][Cc];      // offset_w transposed [o][kk][c]
__device__ float g_Gp[Bb][NCHUNK][Cc*Cc]; // Gram partials
__device__ float g_sup[Bb][NCHUNK][Cc];
__device__ float g_svp[Bb][NCHUNK][Cc];
__device__ float g_G[Bb][Cc*Cc];
__device__ float g_su[Bb][Cc];
__device__ float g_sv[Bb][Cc];
__device__ float g_M[Bb][Cc*Cc];          // attn @ Vw
__device__ float g_r[Bb][Cc];             // attn @ vb

// ------------------------------ K0: weight transposes ------------------------
__global__ void k0_prep(const float* __restrict__ dcn_w,
                        const float* __restrict__ offset_w) {
    int idx = blockIdx.x * blockDim.x + threadIdx.x;
    if (idx < KK9 * Cc * Cc) {
        int kk = idx / (Cc * Cc);
        int rem = idx % (Cc * Cc);
        int c = rem / Cc, co = rem % Cc;
        g_Wt[kk][c][co] = dcn_w[(co * Cc + c) * KK9 + kk];
    }
    if (idx < OCH * KK9 * Cc) {
        int o = idx / (KK9 * Cc);
        int rem = idx % (KK9 * Cc);
        int kk = rem / Cc, c = rem % Cc;
        g_Wo[o][kk][c] = offset_w[(o * Cc + c) * KK9 + kk];
    }
}

// ------------------------------ K2: NCHW -> NHWC -----------------------------
__global__ void k2_transpose(const float* __restrict__ u,
                             const float* __restrict__ v) {
    __shared__ float tile[32][33];
    int img = blockIdx.z;
    int t = img >> 1, b = img & 1;
    const float* x = t ? v : u;
    int n0 = blockIdx.x * 32, c0 = blockIdx.y * 32;
    int tx = threadIdx.x, ty = threadIdx.y;
#pragma unroll
    for (int i = 0; i < 32; i += 8)
        tile[ty + i][tx] = x[(size_t)(b * Cc + c0 + ty + i) * Nn + n0 + tx];
    __syncthreads();
#pragma unroll
    for (int i = 0; i < 32; i += 8)
        g_xnhwc[img][n0 + ty + i][c0 + tx] = tile[tx][ty + i];
}

// ------------------------------ K1: offset conv (3x3, 18 out ch) -------------
// block = one image row (128 pixels, 128 threads). Dynamic smem:
//   sx[3][130][32]  input rows with halo, 32-channel chunk
//   wsm[18][9][32]  weight chunk
__global__ void k1_offset(const float* __restrict__ offset_b) {
    extern __shared__ float sm1[];
    float* sx = sm1;                     // 3*130*32
    float* wsm = sm1 + 3 * 130 * 32;     // 18*9*32
    int y = blockIdx.x, img = blockIdx.y, t = threadIdx.x;
    float acc[OCH];
#pragma unroll
    for (int o = 0; o < OCH; o++) acc[o] = 0.f;

    for (int c0 = 0; c0 < Cc; c0 += 32) {
        __syncthreads();
        for (int idx = t; idx < 3 * 130 * 32; idx += 128) {
            int cc = idx & 31;
            int rest = idx >> 5;
            int s = rest % 130, r = rest / 130;
            int ry = y + r - 1, gx = s - 1;
            float vv = 0.f;
            if (ry >= 0 && ry < Hh && gx >= 0 && gx < Ww)
                vv = g_xnhwc[img][ry * Ww + gx][c0 + cc];
            sx[(r * 130 + s) * 32 + cc] = vv;
        }
        for (int idx = t; idx < OCH * KK9 * 32; idx += 128) {
            int cc = idx & 31;
            int rest = idx >> 5;
            int tap = rest % KK9, o = rest / KK9;
            wsm[(o * KK9 + tap) * 32 + cc] = g_Wo[o][tap][c0 + cc];
        }
        __syncthreads();
        for (int tap = 0; tap < KK9; tap++) {
            int di = tap / 3, dj = tap % 3;
            const float4* xrow = (const float4*)&sx[((di * 130) + t + dj) * 32];
            for (int c4 = 0; c4 < 8; c4++) {
                float4 xv = xrow[c4];
#pragma unroll
                for (int o = 0; o < OCH; o++) {
                    float4 w4 = *(const float4*)&wsm[(o * KK9 + tap) * 32 + c4 * 4];
                    acc[o] += w4.x * xv.x + w4.y * xv.y + w4.z * xv.z + w4.w * xv.w;
                }
            }
        }
    }
    int n = y * Ww + t;
#pragma unroll
    for (int o = 0; o < OCH; o++)
        g_off[img][n][o] = acc[o] + offset_b[o];
}

// ------------------------------ K3: deformable conv --------------------------
// block: 16 pixels (one row segment) x 128 out channels, 256 threads.
// Per tap: bilinear-gather 16x128 samples to smem, then register GEMM.
__global__ void k3_deform(const float* __restrict__ dcn_b) {
    __shared__ int   sbofs[16][KK9][4];
    __shared__ float sbw[16][KK9][4];
    __shared__ float samp[16][Cc];
    int img = blockIdx.y;
    int n0 = blockIdx.x * 16;
    int t = threadIdx.x;

    if (t < 16 * KK9) {
        int p = t / KK9, kk = t % KK9;
        int n = n0 + p, y = n >> 7, x = n & 127;
        float dy = g_off[img][n][kk * 2 + 0];
        float dx = g_off[img][n][kk * 2 + 1];
        float py = (float)(y + kk / 3 - 1) + dy;
        float px = (float)(x + kk % 3 - 1) + dx;
        float y0f = floorf(py), x0f = floorf(px);
        float wy = py - y0f, wx = px - x0f;
        int y0 = (int)y0f, x0 = (int)x0f;
#pragma unroll
        for (int cn = 0; cn < 4; cn++) {
            int a = cn >> 1, bb = cn & 1;
            int yy = y0 + a, xx = x0 + bb;
            bool valid = (yy >= 0 && yy < Hh && xx >= 0 && xx < Ww);
            float wgt = (a ? wy : 1.f - wy) * (bb ? wx : 1.f - wx);
            int yc = min(max(yy, 0), Hh - 1);
            int xc = min(max(xx, 0), Ww - 1);
            sbofs[p][kk][cn] = (yc * Ww + xc) * Cc;
            sbw[p][kk][cn] = valid ? wgt : 0.f;
        }
    }
    float acc[8];
#pragma unroll
    for (int i = 0; i < 8; i++) acc[i] = 0.f;
    int co = t & 127, pg = t >> 7;
    const float* X = &g_xnhwc[img][0][0];
    __syncthreads();

    for (int kk = 0; kk < KK9; kk++) {
#pragma unroll
        for (int r = 0; r < 8; r++) {
            int idx = t + 256 * r;
            int c = idx & 127, p = idx >> 7;
            samp[p][c] = sbw[p][kk][0] * X[sbofs[p][kk][0] + c]
                       + sbw[p][kk][1] * X[sbofs[p][kk][1] + c]
                       + sbw[p][kk][2] * X[sbofs[p][kk][2] + c]
                       + sbw[p][kk][3] * X[sbofs[p][kk][3] + c];
        }
        __syncthreads();
        const float* Wk = &g_Wt[kk][0][0];
        for (int c = 0; c < Cc; c += 4) {
            float w0 = Wk[(c + 0) * Cc + co];
            float w1 = Wk[(c + 1) * Cc + co];
            float w2 = Wk[(c + 2) * Cc + co];
            float w3 = Wk[(c + 3) * Cc + co];
#pragma unroll
            for (int i = 0; i < 8; i++) {
                float4 s4 = *(const float4*)&samp[pg * 8 + i][c];
                acc[i] += w0 * s4.x + w1 * s4.y + w2 * s4.z + w3 * s4.w;
            }
        }
        __syncthreads();
    }
    float bias = dcn_b[co];
#pragma unroll
    for (int i = 0; i < 8; i++)
        g_xd[img][n0 + pg * 8 + i][co] = acc[i] + bias;
}

// ------------------------------ K4: Gram partials G = Ud^T Vd ----------------
__global__ void k4_gpart() {
    extern __shared__ float sm4[];
    float* Us = sm4;               // [128][129]
    float* Vs = sm4 + 128 * 129;   // [128][129]
    int b = blockIdx.y, chunk = blockIdx.x;
    int n0 = chunk * 128, t = threadIdx.x;

    for (int idx = t; idx < 128 * 128; idx += 256) {
        int c = idx & 127, nl = idx >> 7;
        Us[nl * 129 + c] = g_xd[b][n0 + nl][c];
        Vs[nl * 129 + c] = g_xd[2 + b][n0 + nl][c];
    }
    __syncthreads();

    float acc[8][8];
#pragma unroll
    for (int ii = 0; ii < 8; ii++)
#pragma unroll
        for (int jj = 0; jj < 8; jj++) acc[ii][jj] = 0.f;
    int il = t & 15, jl = t >> 4;

    for (int nl = 0; nl < 128; nl++) {
        float av[8], bv[8];
#pragma unroll
        for (int ii = 0; ii < 8; ii++) av[ii] = Us[nl * 129 + il + 16 * ii];
#pragma unroll
        for (int jj = 0; jj < 8; jj++) bv[jj] = Vs[nl * 129 + jl + 16 * jj];
#pragma unroll
        for (int ii = 0; ii < 8; ii++)
#pragma unroll
            for (int jj = 0; jj < 8; jj++) acc[ii][jj] += av[ii] * bv[jj];
    }

    // column sums (for bias terms)
    if (t < 128) {
        float s = 0.f;
        for (int nl = 0; nl < 128; nl++) s += Us[nl * 129 + t];
        g_sup[b][chunk][t] = s;
    } else {
        float s = 0.f;
        int c = t - 128;
        for (int nl = 0; nl < 128; nl++) s += Vs[nl * 129 + c];
        g_svp[b][chunk][c] = s;
    }
    __syncthreads();

    // stage through smem for coalesced global write
#pragma unroll
    for (int ii = 0; ii < 8; ii++)
#pragma unroll
        for (int jj = 0; jj < 8; jj++)
            Us[(il + 16 * ii) * 129 + (jl + 16 * jj)] = acc[ii][jj];
    __syncthreads();
    for (int idx = t; idx < 128 * 128; idx += 256) {
        int j = idx & 127, i = idx >> 7;
        g_Gp[b][chunk][i * 128 + j] = Us[i * 129 + j];
    }
}

// ------------------------------ K4b: reduce partials -------------------------
__global__ void k4b_reduce() {
    int idx = blockIdx.x * 256 + threadIdx.x;
    if (idx < Bb * Cc * Cc) {
        int b = idx >> 14;
        int rem = idx & (Cc * Cc - 1);
        float s = 0.f;
        for (int ch = 0; ch < NCHUNK; ch++) s += g_Gp[b][ch][rem];
        g_G[b][rem] = s;
    } else {
        int k = idx - Bb * Cc * Cc;
        if (k < 2 * Bb * Cc) {
            int sel = k >> 8;
            int b = (k >> 7) & 1;
            int c = k & 127;
            float s = 0.f;
            if (sel) { for (int ch = 0; ch < NCHUNK; ch++) s += g_svp[b][ch][c]; g_sv[b][c] = s; }
            else     { for (int ch = 0; ch < NCHUNK; ch++) s += g_sup[b][ch][c]; g_su[b][c] = s; }
        }
    }
}

// ------------------------------ K5: tiny attention math ----------------------
// logits = Qw G Kw^T + (Qw su) kb^T + qb (Kw sv)^T + N qb kb^T ; softmax ;
// M = attn @ Vw ; r = attn @ vb.  Each block handles 16 attention rows.
__global__ void k5_attn(const float* __restrict__ q_w, const float* __restrict__ q_b,
                        const float* __restrict__ k_w, const float* __restrict__ k_b,
                        const float* __restrict__ v_w, const float* __restrict__ v_b) {
    __shared__ float P[16][128];
    __shared__ float L[16][128];
    __shared__ float ksv[128];
    __shared__ float qsu[16];
    int b = blockIdx.y;
    int i0 = blockIdx.x * 16;
    int t = threadIdx.x;

    if (t < 128) {
        float s = 0.f;
        for (int a = 0; a < 128; a++) s += k_w[t * 128 + a] * g_sv[b][a];
        ksv[t] = s;
    } else if (t < 144) {
        int i = i0 + (t - 128);
        float s = 0.f;
        for (int a = 0; a < 128; a++) s += q_w[i * 128 + a] * g_su[b][a];
        qsu[t - 128] = s;
    }
    __syncthreads();

    for (int idx = t; idx < 16 * 128; idx += 256) {
        int a = idx & 127, ii = idx >> 7;
        int i = i0 + ii;
        float s = 0.f;
        for (int m = 0; m < 128; m++) s += q_w[i * 128 + m] * g_G[b][m * 128 + a];
        P[ii][a] = s;
    }
    __syncthreads();

    const float scale = 0.088388347648318447f; // 128^-0.5
    for (int idx = t; idx < 16 * 128; idx += 256) {
        int j = idx & 127, ii = idx >> 7;
        int i = i0 + ii;
        float s = 0.f;
        for (int a = 0; a < 128; a++) s += P[ii][a] * k_w[j * 128 + a];
        s += qsu[ii] * k_b[j] + q_b[i] * ksv[j] + (float)Nn * q_b[i] * k_b[j];
        L[ii][j] = s * scale;
    }
    __syncthreads();

    if (t < 16) {
        float m = -1e30f;
        for (int j = 0; j < 128; j++) m = fmaxf(m, L[t][j]);
        float s = 0.f;
        for (int j = 0; j < 128; j++) { float e = expf(L[t][j] - m); L[t][j] = e; s += e; }
        float inv = 1.f / s;
        for (int j = 0; j < 128; j++) L[t][j] *= inv;
    }
    __syncthreads();

    for (int idx = t; idx < 16 * 128; idx += 256) {
        int m = idx & 127, ii = idx >> 7;
        float s = 0.f;
        for (int j = 0; j < 128; j++) s += L[ii][j] * v_w[j * 128 + m];
        g_M[b][(i0 + ii) * 128 + m] = s;
    }
    if (t < 16) {
        float s = 0.f;
        for (int j = 0; j < 128; j++) s += L[t][j] * v_b[j];
        g_r[b][i0 + t] = s;
    }
}

// ------------------------------ K6: out = M @ Vd^T + r -----------------------
__global__ void k6_out(float* __restrict__ out) {
    extern __shared__ float sm6[];
    float* Ms = sm6;               // [m][i] pitch 129
    float* Vs = sm6 + 128 * 129;   // [m][nl] pitch 129
    int b = blockIdx.y, n0 = blockIdx.x * 128, t = threadIdx.x;

    for (int idx = t; idx < 128 * 128; idx += 256) {
        int mm = idx & 127, i = idx >> 7;
        Ms[mm * 129 + i] = g_M[b][i * 128 + mm];
    }
    for (int idx = t; idx < 128 * 128; idx += 256) {
        int mm = idx & 127, nl = idx >> 7;
        Vs[mm * 129 + nl] = g_xd[2 + b][n0 + nl][mm];
    }
    __syncthreads();

    float acc[8][8];
#pragma unroll
    for (int ii = 0; ii < 8; ii++)
#pragma unroll
        for (int jj = 0; jj < 8; jj++) acc[ii][jj] = 0.f;
    int il = t & 15, jl = t >> 4;

    for (int mm = 0; mm < 128; mm++) {
        float av[8], bv[8];
#pragma unroll
        for (int ii = 0; ii < 8; ii++) av[ii] = Ms[mm * 129 + il + 16 * ii];
#pragma unroll
        for (int jj = 0; jj < 8; jj++) bv[jj] = Vs[mm * 129 + jl + 16 * jj];
#pragma unroll
        for (int ii = 0; ii < 8; ii++)
#pragma unroll
            for (int jj = 0; jj < 8; jj++) acc[ii][jj] += av[ii] * bv[jj];
    }
    __syncthreads();
#pragma unroll
    for (int ii = 0; ii < 8; ii++)
#pragma unroll
        for (int jj = 0; jj < 8; jj++)
            Ms[(il + 16 * ii) * 129 + (jl + 16 * jj)] = acc[ii][jj];
    __syncthreads();
    for (int idx = t; idx < 128 * 128; idx += 256) {
        int nl = idx & 127, i = idx >> 7;
        out[(size_t)(b * Cc + i) * Nn + n0 + nl] = Ms[i * 129 + nl] + g_r[b][i];
    }
}

// ------------------------------ launch ---------------------------------------
extern "C" void kernel_launch(void* const* d_in, const int* in_sizes, int n_in,
                              void* d_out, int out_size) {
    (void)in_sizes; (void)n_in; (void)out_size;
    const float* u        = (const float*)d_in[0];
    const float* v        = (const float*)d_in[1];
    const float* offset_w = (const float*)d_in[2];
    const float* offset_b = (const float*)d_in[3];
    const float* dcn_w    = (const float*)d_in[4];
    const float* dcn_b    = (const float*)d_in[5];
    const float* q_w      = (const float*)d_in[6];
    const float* q_b      = (const float*)d_in[7];
    const float* k_w      = (const float*)d_in[8];
    const float* k_b      = (const float*)d_in[9];
    const float* v_w      = (const float*)d_in[10];
    const float* v_b      = (const float*)d_in[11];
    float* out = (float*)d_out;

    const int smem_k1 = (3 * 130 * 32 + OCH * KK9 * 32) * 4;   // 70656
    const int smem_big = 2 * 128 * 129 * 4;                    // 132096
    cudaFuncSetAttribute(k1_offset, cudaFuncAttributeMaxDynamicSharedMemorySize, smem_k1);
    cudaFuncSetAttribute(k4_gpart, cudaFuncAttributeMaxDynamicSharedMemorySize, smem_big);
    cudaFuncSetAttribute(k6_out,   cudaFuncAttributeMaxDynamicSharedMemorySize, smem_big);

    k0_prep<<<(KK9 * Cc * Cc + 255) / 256, 256>>>(dcn_w, offset_w);
    k2_transpose<<<dim3(Nn / 32, Cc / 32, NIMG), dim3(32, 8)>>>(u, v);
    k1_offset<<<dim3(Hh, NIMG), 128, smem_k1>>>(offset_b);
    k3_deform<<<dim3(Nn / 16, NIMG), 256>>>(dcn_b);
    k4_gpart<<<dim3(NCHUNK, Bb), 256, smem_big>>>();
    k4b_reduce<<<130, 256>>>();
    k5_attn<<<dim3(8, Bb), 256>>>(q_w, q_b, k_w, k_b, v_w, v_b);
    k6_out<<<dim3(Nn / 128, Bb), 256, smem_big>>>(out);
}

// round 3
// speedup vs baseline: 1.3643x; 1.3643x over previous
#include <cuda_runtime.h>
#include <cuda_fp16.h>
#include <math.h>
#include <stdint.h>

#define Hh 128
#define Ww 128
#define Cc 128
#define Nn (Hh*Ww)
#define Bb 2
#define NIMG 4          // img = tensor*2 + batch ; tensor 0 = u, 1 = v
#define KK9 9
#define OCH 18
#define NCHUNK 128

// -------- scratch (static device allocations; no runtime alloc allowed) ------
__device__ float g_xnhwc[NIMG][Nn][Cc];   // inputs transposed to NHWC
__device__ float g_off[NIMG][Nn][OCH];    // offset conv output, per-pixel 18 vals
__device__ float g_xd[NIMG][Nn][Cc];      // deformable conv outputs (NHWC)
__device__ float g_Wb[KK9][Cc][Cc];       // dcn_w as B operand [kk][co][c]
__device__ float g_Wo[OCH][KK9][Cc];      // offset_w transposed [o][kk][c]
__device__ float g_Gp[Bb][NCHUNK][Cc*Cc]; // Gram partials
__device__ float g_sup[Bb][NCHUNK][Cc];
__device__ float g_svp[Bb][NCHUNK][Cc];
__device__ float g_G[Bb][Cc*Cc];
__device__ float g_su[Bb][Cc];
__device__ float g_sv[Bb][Cc];
__device__ float g_M[Bb][Cc*Cc];          // attn @ Vw
__device__ float g_r[Bb][Cc];             // attn @ vb

// ------------------------------ K0: weight transposes ------------------------
__global__ void k0_prep(const float* __restrict__ dcn_w,
                        const float* __restrict__ offset_w) {
    int idx = blockIdx.x * blockDim.x + threadIdx.x;
    if (idx < KK9 * Cc * Cc) {
        int kk = idx / (Cc * Cc);
        int rem = idx % (Cc * Cc);
        int co = rem >> 7, c = rem & 127;
        g_Wb[kk][co][c] = dcn_w[(co * Cc + c) * KK9 + kk];
    }
    if (idx < OCH * KK9 * Cc) {
        int o = idx / (KK9 * Cc);
        int rem = idx % (KK9 * Cc);
        int kk = rem / Cc, c = rem % Cc;
        g_Wo[o][kk][c] = offset_w[(o * Cc + c) * KK9 + kk];
    }
}

// ------------------------------ K2: NCHW -> NHWC -----------------------------
__global__ void k2_transpose(const float* __restrict__ u,
                             const float* __restrict__ v) {
    __shared__ float tile[32][33];
    int img = blockIdx.z;
    int t = img >> 1, b = img & 1;
    const float* x = t ? v : u;
    int n0 = blockIdx.x * 32, c0 = blockIdx.y * 32;
    int tx = threadIdx.x, ty = threadIdx.y;
#pragma unroll
    for (int i = 0; i < 32; i += 8)
        tile[ty + i][tx] = x[(size_t)(b * Cc + c0 + ty + i) * Nn + n0 + tx];
    __syncthreads();
#pragma unroll
    for (int i = 0; i < 32; i += 8)
        g_xnhwc[img][n0 + ty + i][c0 + tx] = tile[tx][ty + i];
}

// ------------------------------ K1: offset conv (3x3, 18 out ch) -------------
__global__ void k1_offset(const float* __restrict__ offset_b) {
    extern __shared__ float sm1[];
    float* sx = sm1;                     // 3*130*32
    float* wsm = sm1 + 3 * 130 * 32;     // 18*9*32
    int y = blockIdx.x, img = blockIdx.y, t = threadIdx.x;
    float acc[OCH];
#pragma unroll
    for (int o = 0; o < OCH; o++) acc[o] = 0.f;

    for (int c0 = 0; c0 < Cc; c0 += 32) {
        __syncthreads();
        for (int idx = t; idx < 3 * 130 * 32; idx += 128) {
            int cc = idx & 31;
            int rest = idx >> 5;
            int s = rest % 130, r = rest / 130;
            int ry = y + r - 1, gx = s - 1;
            float vv = 0.f;
            if (ry >= 0 && ry < Hh && gx >= 0 && gx < Ww)
                vv = g_xnhwc[img][ry * Ww + gx][c0 + cc];
            sx[(r * 130 + s) * 32 + cc] = vv;
        }
        for (int idx = t; idx < OCH * KK9 * 32; idx += 128) {
            int cc = idx & 31;
            int rest = idx >> 5;
            int tap = rest % KK9, o = rest / KK9;
            wsm[(o * KK9 + tap) * 32 + cc] = g_Wo[o][tap][c0 + cc];
        }
        __syncthreads();
        for (int tap = 0; tap < KK9; tap++) {
            int di = tap / 3, dj = tap % 3;
            const float4* xrow = (const float4*)&sx[((di * 130) + t + dj) * 32];
            for (int c4 = 0; c4 < 8; c4++) {
                float4 xv = xrow[c4];
#pragma unroll
                for (int o = 0; o < OCH; o++) {
                    float4 w4 = *(const float4*)&wsm[(o * KK9 + tap) * 32 + c4 * 4];
                    acc[o] += w4.x * xv.x + w4.y * xv.y + w4.z * xv.z + w4.w * xv.w;
                }
            }
        }
    }
    int n = y * Ww + t;
#pragma unroll
    for (int o = 0; o < OCH; o++)
        g_off[img][n][o] = acc[o] + offset_b[o];
}

// ------------------------------ K3: deformable conv via mma.sync fp16x3 ------
// Block: 128 pixels x 128 out channels, 256 threads (8 warps, m32 x n64 tiles).
// Per tap: bilinear-gather samples -> hi/lo half2 smem tiles; weights likewise;
// 3-pass mma (Ahi*Bhi + Alo*Bhi + Ahi*Blo) accumulating fp32 in registers.
#define PA 68                     // u32 (half2) row pitch: 136 halfs
#define OFF_ALO 34816
#define OFF_BHI 69632
#define OFF_BLO 104448
#define OFF_OFS 139264
#define OFF_WTS 141312
#define K3_DYN  143360

__device__ __forceinline__ void mma16816(float* d, uint32_t a0, uint32_t a1,
                                         uint32_t a2, uint32_t a3,
                                         uint32_t b0, uint32_t b1) {
    asm volatile(
        "mma.sync.aligned.m16n8k16.row.col.f32.f16.f16.f32 "
        "{%0,%1,%2,%3}, {%4,%5,%6,%7}, {%8,%9}, {%0,%1,%2,%3};"
        : "+f"(d[0]), "+f"(d[1]), "+f"(d[2]), "+f"(d[3])
        : "r"(a0), "r"(a1), "r"(a2), "r"(a3), "r"(b0), "r"(b1));
}

__global__ void __launch_bounds__(256, 1) k3_deform(const float* __restrict__ dcn_b) {
    extern __shared__ char B[];
    uint32_t* A32h = (uint32_t*)B;
    uint32_t* A32l = (uint32_t*)(B + OFF_ALO);
    uint32_t* B32h = (uint32_t*)(B + OFF_BHI);
    uint32_t* B32l = (uint32_t*)(B + OFF_BLO);
    int4*   s_ofs = (int4*)(B + OFF_OFS);
    float4* s_w   = (float4*)(B + OFF_WTS);

    int t = threadIdx.x, lane = t & 31, wid = t >> 5;
    int img = blockIdx.y, n0 = blockIdx.x * 128;
    const float* X = &g_xnhwc[img][0][0];

    float acc[2][8][4];
#pragma unroll
    for (int mt = 0; mt < 2; mt++)
#pragma unroll
        for (int nt = 0; nt < 8; nt++)
#pragma unroll
            for (int f = 0; f < 4; f++) acc[mt][nt][f] = 0.f;

    int cpair = t & 63, pxg = t >> 6;        // channel pair 0..63, row group 0..3
    int c = cpair * 2;
    int wm = wid >> 1, wn = wid & 1;         // warp tile coords (4 x 2)

    for (int kk = 0; kk < KK9; kk++) {
        __syncthreads();                      // previous tap's mma reads done
        if (t < 128) {
            int n = n0 + t;
            float dy = g_off[img][n][kk * 2 + 0];
            float dx = g_off[img][n][kk * 2 + 1];
            float py  = (float)((n >> 7) + kk / 3 - 1) + dy;
            float pxf = (float)((n & 127) + kk % 3 - 1) + dx;
            float y0f = floorf(py), x0f = floorf(pxf);
            int y0 = (int)y0f, x0 = (int)x0f;
            float wy = py - y0f, wx = pxf - x0f;
            int y1 = y0 + 1, x1 = x0 + 1;
            bool vy0 = (unsigned)y0 < (unsigned)Hh, vy1 = (unsigned)y1 < (unsigned)Hh;
            bool vx0 = (unsigned)x0 < (unsigned)Ww, vx1 = (unsigned)x1 < (unsigned)Ww;
            int yc0 = min(max(y0, 0), Hh - 1), yc1 = min(max(y1, 0), Hh - 1);
            int xc0 = min(max(x0, 0), Ww - 1), xc1 = min(max(x1, 0), Ww - 1);
            s_ofs[t] = make_int4((yc0 * Ww + xc0) * Cc, (yc0 * Ww + xc1) * Cc,
                                 (yc1 * Ww + xc0) * Cc, (yc1 * Ww + xc1) * Cc);
            s_w[t] = make_float4(vy0 && vx0 ? (1.f - wy) * (1.f - wx) : 0.f,
                                 vy0 && vx1 ? (1.f - wy) * wx : 0.f,
                                 vy1 && vx0 ? wy * (1.f - wx) : 0.f,
                                 vy1 && vx1 ? wy * wx : 0.f);
        }
        __syncthreads();

        // ---- gather A: samples [128 px][128 ch], split hi/lo ----
#pragma unroll 4
        for (int i = 0; i < 32; i++) {
            int px = pxg + i * 4;
            int4  o = s_ofs[px];
            float4 w = s_w[px];
            float2 v0 = *(const float2*)(X + o.x + c);
            float2 v1 = *(const float2*)(X + o.y + c);
            float2 v2 = *(const float2*)(X + o.z + c);
            float2 v3 = *(const float2*)(X + o.w + c);
            float s0 = w.x * v0.x + w.y * v1.x + w.z * v2.x + w.w * v3.x;
            float s1 = w.x * v0.y + w.y * v1.y + w.z * v2.y + w.w * v3.y;
            half2 h = __floats2half2_rn(s0, s1);
            float2 hf = __half22float2(h);
            half2 l = __floats2half2_rn(s0 - hf.x, s1 - hf.y);
            A32h[px * PA + cpair] = *(uint32_t*)&h;
            A32l[px * PA + cpair] = *(uint32_t*)&l;
        }
        // ---- split B: weights [128 co][128 ch] ----
        const float* Wk = &g_Wb[kk][0][0];
#pragma unroll 4
        for (int i = 0; i < 32; i++) {
            int co = pxg + i * 4;
            float2 wv = *(const float2*)(Wk + co * Cc + c);
            half2 h = __floats2half2_rn(wv.x, wv.y);
            float2 hf = __half22float2(h);
            half2 l = __floats2half2_rn(wv.x - hf.x, wv.y - hf.y);
            B32h[co * PA + cpair] = *(uint32_t*)&h;
            B32l[co * PA + cpair] = *(uint32_t*)&l;
        }
        __syncthreads();

        // ---- mma: 8 k16-steps x 3 passes ----
#pragma unroll
        for (int kt = 0; kt < 8; kt++) {
            int kb = kt * 8 + (lane & 3);
            uint32_t ah[2][4], al[2][4];
#pragma unroll
            for (int mt = 0; mt < 2; mt++) {
                int r = wm * 32 + mt * 16 + (lane >> 2);
                ah[mt][0] = A32h[r * PA + kb];
                ah[mt][1] = A32h[(r + 8) * PA + kb];
                ah[mt][2] = A32h[r * PA + kb + 4];
                ah[mt][3] = A32h[(r + 8) * PA + kb + 4];
                al[mt][0] = A32l[r * PA + kb];
                al[mt][1] = A32l[(r + 8) * PA + kb];
                al[mt][2] = A32l[r * PA + kb + 4];
                al[mt][3] = A32l[(r + 8) * PA + kb + 4];
            }
#pragma unroll
            for (int nt = 0; nt < 8; nt++) {
                int nn = wn * 64 + nt * 8 + (lane >> 2);
                uint32_t bh0 = B32h[nn * PA + kb], bh1 = B32h[nn * PA + kb + 4];
                uint32_t bl0 = B32l[nn * PA + kb], bl1 = B32l[nn * PA + kb + 4];
#pragma unroll
                for (int mt = 0; mt < 2; mt++) {
                    mma16816(acc[mt][nt], ah[mt][0], ah[mt][1], ah[mt][2], ah[mt][3], bh0, bh1);
                    mma16816(acc[mt][nt], al[mt][0], al[mt][1], al[mt][2], al[mt][3], bh0, bh1);
                    mma16816(acc[mt][nt], ah[mt][0], ah[mt][1], ah[mt][2], ah[mt][3], bl0, bl1);
                }
            }
        }
    }

    // ---- epilogue: bias + direct store (C frag: c0,c1 = cols 2j,2j+1) ----
#pragma unroll
    for (int mt = 0; mt < 2; mt++) {
        int r0 = wm * 32 + mt * 16 + (lane >> 2);
#pragma unroll
        for (int nt = 0; nt < 8; nt++) {
            int col = wn * 64 + nt * 8 + (lane & 3) * 2;
            float2 bias = *(const float2*)(dcn_b + col);
            float2 o0 = make_float2(acc[mt][nt][0] + bias.x, acc[mt][nt][1] + bias.y);
            float2 o1 = make_float2(acc[mt][nt][2] + bias.x, acc[mt][nt][3] + bias.y);
            *(float2*)&g_xd[img][n0 + r0][col] = o0;
            *(float2*)&g_xd[img][n0 + r0 + 8][col] = o1;
        }
    }
}

// ------------------------------ K4: Gram partials G = Ud^T Vd ----------------
__global__ void k4_gpart() {
    extern __shared__ float sm4[];
    float* Us = sm4;               // [128][129]
    float* Vs = sm4 + 128 * 129;   // [128][129]
    int b = blockIdx.y, chunk = blockIdx.x;
    int n0 = chunk * 128, t = threadIdx.x;

    for (int idx = t; idx < 128 * 128; idx += 256) {
        int c = idx & 127, nl = idx >> 7;
        Us[nl * 129 + c] = g_xd[b][n0 + nl][c];
        Vs[nl * 129 + c] = g_xd[2 + b][n0 + nl][c];
    }
    __syncthreads();

    float acc[8][8];
#pragma unroll
    for (int ii = 0; ii < 8; ii++)
#pragma unroll
        for (int jj = 0; jj < 8; jj++) acc[ii][jj] = 0.f;
    int il = t & 15, jl = t >> 4;

    for (int nl = 0; nl < 128; nl++) {
        float av[8], bv[8];
#pragma unroll
        for (int ii = 0; ii < 8; ii++) av[ii] = Us[nl * 129 + il + 16 * ii];
#pragma unroll
        for (int jj = 0; jj < 8; jj++) bv[jj] = Vs[nl * 129 + jl + 16 * jj];
#pragma unroll
        for (int ii = 0; ii < 8; ii++)
#pragma unroll
            for (int jj = 0; jj < 8; jj++) acc[ii][jj] += av[ii] * bv[jj];
    }

    if (t < 128) {
        float s = 0.f;
        for (int nl = 0; nl < 128; nl++) s += Us[nl * 129 + t];
        g_sup[b][chunk][t] = s;
    } else {
        float s = 0.f;
        int c = t - 128;
        for (int nl = 0; nl < 128; nl++) s += Vs[nl * 129 + c];
        g_svp[b][chunk][c] = s;
    }
    __syncthreads();

#pragma unroll
    for (int ii = 0; ii < 8; ii++)
#pragma unroll
        for (int jj = 0; jj < 8; jj++)
            Us[(il + 16 * ii) * 129 + (jl + 16 * jj)] = acc[ii][jj];
    __syncthreads();
    for (int idx = t; idx < 128 * 128; idx += 256) {
        int j = idx & 127, i = idx >> 7;
        g_Gp[b][chunk][i * 128 + j] = Us[i * 129 + j];
    }
}

// ------------------------------ K4b: reduce partials -------------------------
__global__ void k4b_reduce() {
    int idx = blockIdx.x * 256 + threadIdx.x;
    if (idx < Bb * Cc * Cc) {
        int b = idx >> 14;
        int rem = idx & (Cc * Cc - 1);
        float s = 0.f;
        for (int ch = 0; ch < NCHUNK; ch++) s += g_Gp[b][ch][rem];
        g_G[b][rem] = s;
    } else {
        int k = idx - Bb * Cc * Cc;
        if (k < 2 * Bb * Cc) {
            int sel = k >> 8;
            int b = (k >> 7) & 1;
            int c = k & 127;
            float s = 0.f;
            if (sel) { for (int ch = 0; ch < NCHUNK; ch++) s += g_svp[b][ch][c]; g_sv[b][c] = s; }
            else     { for (int ch = 0; ch < NCHUNK; ch++) s += g_sup[b][ch][c]; g_su[b][c] = s; }
        }
    }
}

// ------------------------------ K5: tiny attention math ----------------------
__global__ void k5_attn(const float* __restrict__ q_w, const float* __restrict__ q_b,
                        const float* __restrict__ k_w, const float* __restrict__ k_b,
                        const float* __restrict__ v_w, const float* __restrict__ v_b) {
    __shared__ float P[16][128];
    __shared__ float L[16][128];
    __shared__ float ksv[128];
    __shared__ float qsu[16];
    int b = blockIdx.y;
    int i0 = blockIdx.x * 16;
    int t = threadIdx.x;

    if (t < 128) {
        float s = 0.f;
        for (int a = 0; a < 128; a++) s += k_w[t * 128 + a] * g_sv[b][a];
        ksv[t] = s;
    } else if (t < 144) {
        int i = i0 + (t - 128);
        float s = 0.f;
        for (int a = 0; a < 128; a++) s += q_w[i * 128 + a] * g_su[b][a];
        qsu[t - 128] = s;
    }
    __syncthreads();

    for (int idx = t; idx < 16 * 128; idx += 256) {
        int a = idx & 127, ii = idx >> 7;
        int i = i0 + ii;
        float s = 0.f;
        for (int m = 0; m < 128; m++) s += q_w[i * 128 + m] * g_G[b][m * 128 + a];
        P[ii][a] = s;
    }
    __syncthreads();

    const float scale = 0.088388347648318447f; // 128^-0.5
    for (int idx = t; idx < 16 * 128; idx += 256) {
        int j = idx & 127, ii = idx >> 7;
        int i = i0 + ii;
        float s = 0.f;
        for (int a = 0; a < 128; a++) s += P[ii][a] * k_w[j * 128 + a];
        s += qsu[ii] * k_b[j] + q_b[i] * ksv[j] + (float)Nn * q_b[i] * k_b[j];
        L[ii][j] = s * scale;
    }
    __syncthreads();

    if (t < 16) {
        float m = -1e30f;
        for (int j = 0; j < 128; j++) m = fmaxf(m, L[t][j]);
        float s = 0.f;
        for (int j = 0; j < 128; j++) { float e = expf(L[t][j] - m); L[t][j] = e; s += e; }
        float inv = 1.f / s;
        for (int j = 0; j < 128; j++) L[t][j] *= inv;
    }
    __syncthreads();

    for (int idx = t; idx < 16 * 128; idx += 256) {
        int m = idx & 127, ii = idx >> 7;
        float s = 0.f;
        for (int j = 0; j < 128; j++) s += L[ii][j] * v_w[j * 128 + m];
        g_M[b][(i0 + ii) * 128 + m] = s;
    }
    if (t < 16) {
        float s = 0.f;
        for (int j = 0; j < 128; j++) s += L[t][j] * v_b[j];
        g_r[b][i0 + t] = s;
    }
}

// ------------------------------ K6: out = M @ Vd^T + r -----------------------
__global__ void k6_out(float* __restrict__ out) {
    extern __shared__ float sm6[];
    float* Ms = sm6;               // [m][i] pitch 129
    float* Vs = sm6 + 128 * 129;   // [m][nl] pitch 129
    int b = blockIdx.y, n0 = blockIdx.x * 128, t = threadIdx.x;

    for (int idx = t; idx < 128 * 128; idx += 256) {
        int mm = idx & 127, i = idx >> 7;
        Ms[mm * 129 + i] = g_M[b][i * 128 + mm];
    }
    for (int idx = t; idx < 128 * 128; idx += 256) {
        int mm = idx & 127, nl = idx >> 7;
        Vs[mm * 129 + nl] = g_xd[2 + b][n0 + nl][mm];
    }
    __syncthreads();

    float acc[8][8];
#pragma unroll
    for (int ii = 0; ii < 8; ii++)
#pragma unroll
        for (int jj = 0; jj < 8; jj++) acc[ii][jj] = 0.f;
    int il = t & 15, jl = t >> 4;

    for (int mm = 0; mm < 128; mm++) {
        float av[8], bv[8];
#pragma unroll
        for (int ii = 0; ii < 8; ii++) av[ii] = Ms[mm * 129 + il + 16 * ii];
#pragma unroll
        for (int jj = 0; jj < 8; jj++) bv[jj] = Vs[mm * 129 + jl + 16 * jj];
#pragma unroll
        for (int ii = 0; ii < 8; ii++)
#pragma unroll
            for (int jj = 0; jj < 8; jj++) acc[ii][jj] += av[ii] * bv[jj];
    }
    __syncthreads();
#pragma unroll
    for (int ii = 0; ii < 8; ii++)
#pragma unroll
        for (int jj = 0; jj < 8; jj++)
            Ms[(il + 16 * ii) * 129 + (jl + 16 * jj)] = acc[ii][jj];
    __syncthreads();
    for (int idx = t; idx < 128 * 128; idx += 256) {
        int nl = idx & 127, i = idx >> 7;
        out[(size_t)(b * Cc + i) * Nn + n0 + nl] = Ms[i * 129 + nl] + g_r[b][i];
    }
}

// ------------------------------ launch ---------------------------------------
extern "C" void kernel_launch(void* const* d_in, const int* in_sizes, int n_in,
                              void* d_out, int out_size) {
    (void)in_sizes; (void)n_in; (void)out_size;
    const float* u        = (const float*)d_in[0];
    const float* v        = (const float*)d_in[1];
    const float* offset_w = (const float*)d_in[2];
    const float* offset_b = (const float*)d_in[3];
    const float* dcn_w    = (const float*)d_in[4];
    const float* dcn_b    = (const float*)d_in[5];
    const float* q_w      = (const float*)d_in[6];
    const float* q_b      = (const float*)d_in[7];
    const float* k_w      = (const float*)d_in[8];
    const float* k_b      = (const float*)d_in[9];
    const float* v_w      = (const float*)d_in[10];
    const float* v_b      = (const float*)d_in[11];
    float* out = (float*)d_out;

    const int smem_k1 = (3 * 130 * 32 + OCH * KK9 * 32) * 4;   // 70656
    const int smem_big = 2 * 128 * 129 * 4;                    // 132096
    cudaFuncSetAttribute(k1_offset, cudaFuncAttributeMaxDynamicSharedMemorySize, smem_k1);
    cudaFuncSetAttribute(k3_deform, cudaFuncAttributeMaxDynamicSharedMemorySize, K3_DYN);
    cudaFuncSetAttribute(k4_gpart, cudaFuncAttributeMaxDynamicSharedMemorySize, smem_big);
    cudaFuncSetAttribute(k6_out,   cudaFuncAttributeMaxDynamicSharedMemorySize, smem_big);

    k0_prep<<<(KK9 * Cc * Cc + 255) / 256, 256>>>(dcn_w, offset_w);
    k2_transpose<<<dim3(Nn / 32, Cc / 32, NIMG), dim3(32, 8)>>>(u, v);
    k1_offset<<<dim3(Hh, NIMG), 128, smem_k1>>>(offset_b);
    k3_deform<<<dim3(Nn / 128, NIMG), 256, K3_DYN>>>(dcn_b);
    k4_gpart<<<dim3(NCHUNK, Bb), 256, smem_big>>>();
    k4b_reduce<<<130, 256>>>();
    k5_attn<<<dim3(8, Bb), 256>>>(q_w, q_b, k_w, k_b, v_w, v_b);
    k6_out<<<dim3(Nn / 128, Bb), 256, smem_big>>>(out);
}

// round 4
// speedup vs baseline: 1.5629x; 1.1456x over previous
#include <cuda_runtime.h>
#include <cuda_fp16.h>
#include <math.h>
#include <stdint.h>

#define Hh 128
#define Ww 128
#define Cc 128
#define Nn (Hh*Ww)
#define Bb 2
#define NIMG 4          // img = tensor*2 + batch ; tensor 0 = u, 1 = v
#define KK9 9
#define OCH 18
#define NCHUNK 128

// -------- scratch (static device allocations; no runtime alloc allowed) ------
__device__ float g_xnhwc[NIMG][Nn][Cc];   // inputs transposed to NHWC
__device__ float g_off[NIMG][Nn][OCH];    // offset conv output, per-pixel 18 vals
__device__ float g_xd[NIMG][Nn][Cc];      // deformable conv outputs (NHWC)
__device__ __half g_Wh[KK9][Cc][Cc];      // dcn_w hi-half [kk][co][c]
__device__ __half g_Wl[KK9][Cc][Cc];      // dcn_w lo-half
__device__ float g_Wo[OCH][KK9][Cc];      // offset_w transposed [o][kk][c]
__device__ float g_Gp[Bb][NCHUNK][Cc*Cc]; // Gram partials
__device__ float g_sup[Bb][NCHUNK][Cc];
__device__ float g_svp[Bb][NCHUNK][Cc];
__device__ float g_G[Bb][Cc*Cc];
__device__ float g_su[Bb][Cc];
__device__ float g_sv[Bb][Cc];
__device__ float g_M[Bb][Cc*Cc];          // attn @ Vw
__device__ float g_r[Bb][Cc];             // attn @ vb

// ------------------------------ K0: weight prep ------------------------------
__global__ void k0_prep(const float* __restrict__ dcn_w,
                        const float* __restrict__ offset_w) {
    int idx = blockIdx.x * blockDim.x + threadIdx.x;
    if (idx < KK9 * Cc * Cc) {
        int kk = idx / (Cc * Cc);
        int rem = idx % (Cc * Cc);
        int co = rem >> 7, c = rem & 127;
        float w = dcn_w[(co * Cc + c) * KK9 + kk];
        __half h = __float2half_rn(w);
        __half l = __float2half_rn(w - __half2float(h));
        g_Wh[kk][co][c] = h;
        g_Wl[kk][co][c] = l;
    }
    if (idx < OCH * KK9 * Cc) {
        int o = idx / (KK9 * Cc);
        int rem = idx % (KK9 * Cc);
        int kk = rem / Cc, c = rem % Cc;
        g_Wo[o][kk][c] = offset_w[(o * Cc + c) * KK9 + kk];
    }
}

// ------------------------------ K2: NCHW -> NHWC -----------------------------
__global__ void k2_transpose(const float* __restrict__ u,
                             const float* __restrict__ v) {
    __shared__ float tile[32][33];
    int img = blockIdx.z;
    int t = img >> 1, b = img & 1;
    const float* x = t ? v : u;
    int n0 = blockIdx.x * 32, c0 = blockIdx.y * 32;
    int tx = threadIdx.x, ty = threadIdx.y;
#pragma unroll
    for (int i = 0; i < 32; i += 8)
        tile[ty + i][tx] = x[(size_t)(b * Cc + c0 + ty + i) * Nn + n0 + tx];
    __syncthreads();
#pragma unroll
    for (int i = 0; i < 32; i += 8)
        g_xnhwc[img][n0 + ty + i][c0 + tx] = tile[tx][ty + i];
}

// ------------------------------ K1: offset conv (3x3, 18 out ch) -------------
__global__ void k1_offset(const float* __restrict__ offset_b) {
    extern __shared__ float sm1[];
    float* sx = sm1;                     // 3*130*32
    float* wsm = sm1 + 3 * 130 * 32;     // 18*9*32
    int y = blockIdx.x, img = blockIdx.y, t = threadIdx.x;
    float acc[OCH];
#pragma unroll
    for (int o = 0; o < OCH; o++) acc[o] = 0.f;

    for (int c0 = 0; c0 < Cc; c0 += 32) {
        __syncthreads();
        for (int idx = t; idx < 3 * 130 * 32; idx += 128) {
            int cc = idx & 31;
            int rest = idx >> 5;
            int s = rest % 130, r = rest / 130;
            int ry = y + r - 1, gx = s - 1;
            float vv = 0.f;
            if (ry >= 0 && ry < Hh && gx >= 0 && gx < Ww)
                vv = g_xnhwc[img][ry * Ww + gx][c0 + cc];
            sx[(r * 130 + s) * 32 + cc] = vv;
        }
        for (int idx = t; idx < OCH * KK9 * 32; idx += 128) {
            int cc = idx & 31;
            int rest = idx >> 5;
            int tap = rest % KK9, o = rest / KK9;
            wsm[(o * KK9 + tap) * 32 + cc] = g_Wo[o][tap][c0 + cc];
        }
        __syncthreads();
        for (int tap = 0; tap < KK9; tap++) {
            int di = tap / 3, dj = tap % 3;
            const float4* xrow = (const float4*)&sx[((di * 130) + t + dj) * 32];
            for (int c4 = 0; c4 < 8; c4++) {
                float4 xv = xrow[c4];
#pragma unroll
                for (int o = 0; o < OCH; o++) {
                    float4 w4 = *(const float4*)&wsm[(o * KK9 + tap) * 32 + c4 * 4];
                    acc[o] += w4.x * xv.x + w4.y * xv.y + w4.z * xv.z + w4.w * xv.w;
                }
            }
        }
    }
    int n = y * Ww + t;
#pragma unroll
    for (int o = 0; o < OCH; o++)
        g_off[img][n][o] = acc[o] + offset_b[o];
}

// ------------------------------ K3: deformable conv via mma.sync fp16x3 ------
// Block: 128 px x 128 co, 512 threads (16 warps, m32 x n32 tiles).
// A (samples): gathered+split per tap into smem. B (weights): precomputed hi/lo
// halves in global, streamed via cp.async, double-buffered across taps.
#define PA 68                       // u32 row pitch (136 halfs)
#define MATB (128 * PA * 4)         // 34816 bytes per half-matrix
#define OFF_ALO  MATB
#define OFF_B0   (2 * MATB)         // buffer0: hi at +0, lo at +MATB
#define OFF_B1   (4 * MATB)
#define OFF_OFS  (6 * MATB)         // int4[128]
#define OFF_WTS  (6 * MATB + 2048)  // float4[128]
#define K3_DYN   (6 * MATB + 4096)  // 212992

__device__ __forceinline__ void mma16816(float* d, uint32_t a0, uint32_t a1,
                                         uint32_t a2, uint32_t a3,
                                         uint32_t b0, uint32_t b1) {
    asm volatile(
        "mma.sync.aligned.m16n8k16.row.col.f32.f16.f16.f32 "
        "{%0,%1,%2,%3}, {%4,%5,%6,%7}, {%8,%9}, {%0,%1,%2,%3};"
        : "+f"(d[0]), "+f"(d[1]), "+f"(d[2]), "+f"(d[3])
        : "r"(a0), "r"(a1), "r"(a2), "r"(a3), "r"(b0), "r"(b1));
}
__device__ __forceinline__ uint32_t smem_u32(const void* p) {
    uint32_t a;
    asm("{ .reg .u64 t; cvta.to.shared.u64 t, %1; cvt.u32.u64 %0, t; }" : "=r"(a) : "l"(p));
    return a;
}
__device__ __forceinline__ void cp16(uint32_t s, const void* g) {
    asm volatile("cp.async.cg.shared.global [%0], [%1], 16;" :: "r"(s), "l"(g));
}

// prefetch one tap's B (hi+lo) into buffer buf; 8 chunks of 16B per thread
__device__ __forceinline__ void prefetch_B(char* B, uint32_t sb, int buf, int kk, int t) {
    uint32_t base = sb + OFF_B0 + buf * (2 * MATB);
#pragma unroll
    for (int j = 0; j < 8; j++) {
        int chunk = t + 512 * j;              // 0..4095
        int lo = chunk >> 11;                 // 0: hi, 1: lo
        int cc = chunk & 2047;
        int row = cc >> 4, ch16 = cc & 15;
        const __half* gsrc = lo ? &g_Wl[kk][row][ch16 * 8] : &g_Wh[kk][row][ch16 * 8];
        cp16(base + lo * MATB + (row * PA + ch16 * 4) * 4, gsrc);
    }
    asm volatile("cp.async.commit_group;" ::: "memory");
}

__global__ void __launch_bounds__(512, 1) k3_deform(const float* __restrict__ dcn_b) {
    extern __shared__ char B[];
    uint32_t sb = smem_u32(B);
    uint32_t* A32h = (uint32_t*)B;
    uint32_t* A32l = (uint32_t*)(B + OFF_ALO);
    int4*   s_ofs = (int4*)(B + OFF_OFS);
    float4* s_w   = (float4*)(B + OFF_WTS);

    int t = threadIdx.x, lane = t & 31, wid = t >> 5;
    int img = blockIdx.y, n0 = blockIdx.x * 128;
    const float* X = &g_xnhwc[img][0][0];

    float acc[2][4][4];
#pragma unroll
    for (int mt = 0; mt < 2; mt++)
#pragma unroll
        for (int nt = 0; nt < 4; nt++)
#pragma unroll
            for (int f = 0; f < 4; f++) acc[mt][nt][f] = 0.f;

    int cpair = t & 63, pxg = t >> 6;        // channel pair 0..63, px group 0..7
    int c = cpair * 2;
    int wm = wid >> 2, wn = wid & 3;         // warp tile coords (4 x 4)

    prefetch_B(B, sb, 0, 0, t);

    for (int kk = 0; kk < KK9; kk++) {
        __syncthreads();                      // previous tap's mma reads done
        int buf = kk & 1;
        if (kk < KK9 - 1) prefetch_B(B, sb, buf ^ 1, kk + 1, t);

        if (t < 128) {
            int n = n0 + t;
            float dy = g_off[img][n][kk * 2 + 0];
            float dx = g_off[img][n][kk * 2 + 1];
            float py  = (float)((n >> 7) + kk / 3 - 1) + dy;
            float pxf = (float)((n & 127) + kk % 3 - 1) + dx;
            float y0f = floorf(py), x0f = floorf(pxf);
            int y0 = (int)y0f, x0 = (int)x0f;
            float wy = py - y0f, wx = pxf - x0f;
            int y1 = y0 + 1, x1 = x0 + 1;
            bool vy0 = (unsigned)y0 < (unsigned)Hh, vy1 = (unsigned)y1 < (unsigned)Hh;
            bool vx0 = (unsigned)x0 < (unsigned)Ww, vx1 = (unsigned)x1 < (unsigned)Ww;
            int yc0 = min(max(y0, 0), Hh - 1), yc1 = min(max(y1, 0), Hh - 1);
            int xc0 = min(max(x0, 0), Ww - 1), xc1 = min(max(x1, 0), Ww - 1);
            s_ofs[t] = make_int4((yc0 * Ww + xc0) * Cc, (yc0 * Ww + xc1) * Cc,
                                 (yc1 * Ww + xc0) * Cc, (yc1 * Ww + xc1) * Cc);
            s_w[t] = make_float4(vy0 && vx0 ? (1.f - wy) * (1.f - wx) : 0.f,
                                 vy0 && vx1 ? (1.f - wy) * wx : 0.f,
                                 vy1 && vx0 ? wy * (1.f - wx) : 0.f,
                                 vy1 && vx1 ? wy * wx : 0.f);
        }
        __syncthreads();

        // ---- gather A: samples [128 px][128 ch], split hi/lo ----
#pragma unroll 4
        for (int i = 0; i < 16; i++) {
            int px = pxg + i * 8;
            int4  o = s_ofs[px];
            float4 w = s_w[px];
            float2 v0 = *(const float2*)(X + o.x + c);
            float2 v1 = *(const float2*)(X + o.y + c);
            float2 v2 = *(const float2*)(X + o.z + c);
            float2 v3 = *(const float2*)(X + o.w + c);
            float s0 = w.x * v0.x + w.y * v1.x + w.z * v2.x + w.w * v3.x;
            float s1 = w.x * v0.y + w.y * v1.y + w.z * v2.y + w.w * v3.y;
            half2 h = __floats2half2_rn(s0, s1);
            float2 hf = __half22float2(h);
            half2 l = __floats2half2_rn(s0 - hf.x, s1 - hf.y);
            A32h[px * PA + cpair] = *(uint32_t*)&h;
            A32l[px * PA + cpair] = *(uint32_t*)&l;
        }
        // wait for this tap's B tiles (at most the k+1 prefetch stays pending)
        if (kk < KK9 - 1)
            asm volatile("cp.async.wait_group 1;" ::: "memory");
        else
            asm volatile("cp.async.wait_group 0;" ::: "memory");
        __syncthreads();

        const uint32_t* B32h = (const uint32_t*)(B + OFF_B0 + buf * (2 * MATB));
        const uint32_t* B32l = B32h + 128 * PA;

        // ---- mma: 8 k16-steps x 3 passes ----
#pragma unroll
        for (int kt = 0; kt < 8; kt++) {
            int kb = kt * 8 + (lane & 3);
            uint32_t ah[2][4], al[2][4];
#pragma unroll
            for (int mt = 0; mt < 2; mt++) {
                int r = wm * 32 + mt * 16 + (lane >> 2);
                ah[mt][0] = A32h[r * PA + kb];
                ah[mt][1] = A32h[(r + 8) * PA + kb];
                ah[mt][2] = A32h[r * PA + kb + 4];
                ah[mt][3] = A32h[(r + 8) * PA + kb + 4];
                al[mt][0] = A32l[r * PA + kb];
                al[mt][1] = A32l[(r + 8) * PA + kb];
                al[mt][2] = A32l[r * PA + kb + 4];
                al[mt][3] = A32l[(r + 8) * PA + kb + 4];
            }
#pragma unroll
            for (int nt = 0; nt < 4; nt++) {
                int nn = wn * 32 + nt * 8 + (lane >> 2);
                uint32_t bh0 = B32h[nn * PA + kb], bh1 = B32h[nn * PA + kb + 4];
                uint32_t bl0 = B32l[nn * PA + kb], bl1 = B32l[nn * PA + kb + 4];
#pragma unroll
                for (int mt = 0; mt < 2; mt++) {
                    mma16816(acc[mt][nt], ah[mt][0], ah[mt][1], ah[mt][2], ah[mt][3], bh0, bh1);
                    mma16816(acc[mt][nt], al[mt][0], al[mt][1], al[mt][2], al[mt][3], bh0, bh1);
                    mma16816(acc[mt][nt], ah[mt][0], ah[mt][1], ah[mt][2], ah[mt][3], bl0, bl1);
                }
            }
        }
    }

    // ---- epilogue: bias + direct store ----
#pragma unroll
    for (int mt = 0; mt < 2; mt++) {
        int r0 = wm * 32 + mt * 16 + (lane >> 2);
#pragma unroll
        for (int nt = 0; nt < 4; nt++) {
            int col = wn * 32 + nt * 8 + (lane & 3) * 2;
            float2 bias = *(const float2*)(dcn_b + col);
            float2 o0 = make_float2(acc[mt][nt][0] + bias.x, acc[mt][nt][1] + bias.y);
            float2 o1 = make_float2(acc[mt][nt][2] + bias.x, acc[mt][nt][3] + bias.y);
            *(float2*)&g_xd[img][n0 + r0][col] = o0;
            *(float2*)&g_xd[img][n0 + r0 + 8][col] = o1;
        }
    }
}

// ------------------------------ K4: Gram partials G = Ud^T Vd ----------------
__global__ void k4_gpart() {
    extern __shared__ float sm4[];
    float* Us = sm4;               // [128][129]
    float* Vs = sm4 + 128 * 129;   // [128][129]
    int b = blockIdx.y, chunk = blockIdx.x;
    int n0 = chunk * 128, t = threadIdx.x;

    for (int idx = t; idx < 128 * 128; idx += 256) {
        int c = idx & 127, nl = idx >> 7;
        Us[nl * 129 + c] = g_xd[b][n0 + nl][c];
        Vs[nl * 129 + c] = g_xd[2 + b][n0 + nl][c];
    }
    __syncthreads();

    float acc[8][8];
#pragma unroll
    for (int ii = 0; ii < 8; ii++)
#pragma unroll
        for (int jj = 0; jj < 8; jj++) acc[ii][jj] = 0.f;
    int il = t & 15, jl = t >> 4;

    for (int nl = 0; nl < 128; nl++) {
        float av[8], bv[8];
#pragma unroll
        for (int ii = 0; ii < 8; ii++) av[ii] = Us[nl * 129 + il + 16 * ii];
#pragma unroll
        for (int jj = 0; jj < 8; jj++) bv[jj] = Vs[nl * 129 + jl + 16 * jj];
#pragma unroll
        for (int ii = 0; ii < 8; ii++)
#pragma unroll
            for (int jj = 0; jj < 8; jj++) acc[ii][jj] += av[ii] * bv[jj];
    }

    if (t < 128) {
        float s = 0.f;
        for (int nl = 0; nl < 128; nl++) s += Us[nl * 129 + t];
        g_sup[b][chunk][t] = s;
    } else {
        float s = 0.f;
        int c = t - 128;
        for (int nl = 0; nl < 128; nl++) s += Vs[nl * 129 + c];
        g_svp[b][chunk][c] = s;
    }
    __syncthreads();

#pragma unroll
    for (int ii = 0; ii < 8; ii++)
#pragma unroll
        for (int jj = 0; jj < 8; jj++)
            Us[(il + 16 * ii) * 129 + (jl + 16 * jj)] = acc[ii][jj];
    __syncthreads();
    for (int idx = t; idx < 128 * 128; idx += 256) {
        int j = idx & 127, i = idx >> 7;
        g_Gp[b][chunk][i * 128 + j] = Us[i * 129 + j];
    }
}

// ------------------------------ K4b: reduce partials -------------------------
__global__ void k4b_reduce() {
    int idx = blockIdx.x * 256 + threadIdx.x;
    if (idx < Bb * Cc * Cc) {
        int b = idx >> 14;
        int rem = idx & (Cc * Cc - 1);
        float s = 0.f;
        for (int ch = 0; ch < NCHUNK; ch++) s += g_Gp[b][ch][rem];
        g_G[b][rem] = s;
    } else {
        int k = idx - Bb * Cc * Cc;
        if (k < 2 * Bb * Cc) {
            int sel = k >> 8;
            int b = (k >> 7) & 1;
            int c = k & 127;
            float s = 0.f;
            if (sel) { for (int ch = 0; ch < NCHUNK; ch++) s += g_svp[b][ch][c]; g_sv[b][c] = s; }
            else     { for (int ch = 0; ch < NCHUNK; ch++) s += g_sup[b][ch][c]; g_su[b][c] = s; }
        }
    }
}

// ------------------------------ K5: tiny attention math ----------------------
__global__ void k5_attn(const float* __restrict__ q_w, const float* __restrict__ q_b,
                        const float* __restrict__ k_w, const float* __restrict__ k_b,
                        const float* __restrict__ v_w, const float* __restrict__ v_b) {
    __shared__ float P[16][128];
    __shared__ float L[16][128];
    __shared__ float ksv[128];
    __shared__ float qsu[16];
    int b = blockIdx.y;
    int i0 = blockIdx.x * 16;
    int t = threadIdx.x;

    if (t < 128) {
        float s = 0.f;
        for (int a = 0; a < 128; a++) s += k_w[t * 128 + a] * g_sv[b][a];
        ksv[t] = s;
    } else if (t < 144) {
        int i = i0 + (t - 128);
        float s = 0.f;
        for (int a = 0; a < 128; a++) s += q_w[i * 128 + a] * g_su[b][a];
        qsu[t - 128] = s;
    }
    __syncthreads();

    for (int idx = t; idx < 16 * 128; idx += 256) {
        int a = idx & 127, ii = idx >> 7;
        int i = i0 + ii;
        float s = 0.f;
        for (int m = 0; m < 128; m++) s += q_w[i * 128 + m] * g_G[b][m * 128 + a];
        P[ii][a] = s;
    }
    __syncthreads();

    const float scale = 0.088388347648318447f; // 128^-0.5
    for (int idx = t; idx < 16 * 128; idx += 256) {
        int j = idx & 127, ii = idx >> 7;
        int i = i0 + ii;
        float s = 0.f;
        for (int a = 0; a < 128; a++) s += P[ii][a] * k_w[j * 128 + a];
        s += qsu[ii] * k_b[j] + q_b[i] * ksv[j] + (float)Nn * q_b[i] * k_b[j];
        L[ii][j] = s * scale;
    }
    __syncthreads();

    if (t < 16) {
        float m = -1e30f;
        for (int j = 0; j < 128; j++) m = fmaxf(m, L[t][j]);
        float s = 0.f;
        for (int j = 0; j < 128; j++) { float e = expf(L[t][j] - m); L[t][j] = e; s += e; }
        float inv = 1.f / s;
        for (int j = 0; j < 128; j++) L[t][j] *= inv;
    }
    __syncthreads();

    for (int idx = t; idx < 16 * 128; idx += 256) {
        int m = idx & 127, ii = idx >> 7;
        float s = 0.f;
        for (int j = 0; j < 128; j++) s += L[ii][j] * v_w[j * 128 + m];
        g_M[b][(i0 + ii) * 128 + m] = s;
    }
    if (t < 16) {
        float s = 0.f;
        for (int j = 0; j < 128; j++) s += L[t][j] * v_b[j];
        g_r[b][i0 + t] = s;
    }
}

// ------------------------------ K6: out = M @ Vd^T + r -----------------------
__global__ void k6_out(float* __restrict__ out) {
    extern __shared__ float sm6[];
    float* Ms = sm6;               // [m][i] pitch 129
    float* Vs = sm6 + 128 * 129;   // [m][nl] pitch 129
    int b = blockIdx.y, n0 = blockIdx.x * 128, t = threadIdx.x;

    for (int idx = t; idx < 128 * 128; idx += 256) {
        int mm = idx & 127, i = idx >> 7;
        Ms[mm * 129 + i] = g_M[b][i * 128 + mm];
    }
    for (int idx = t; idx < 128 * 128; idx += 256) {
        int mm = idx & 127, nl = idx >> 7;
        Vs[mm * 129 + nl] = g_xd[2 + b][n0 + nl][mm];
    }
    __syncthreads();

    float acc[8][8];
#pragma unroll
    for (int ii = 0; ii < 8; ii++)
#pragma unroll
        for (int jj = 0; jj < 8; jj++) acc[ii][jj] = 0.f;
    int il = t & 15, jl = t >> 4;

    for (int mm = 0; mm < 128; mm++) {
        float av[8], bv[8];
#pragma unroll
        for (int ii = 0; ii < 8; ii++) av[ii] = Ms[mm * 129 + il + 16 * ii];
#pragma unroll
        for (int jj = 0; jj < 8; jj++) bv[jj] = Vs[mm * 129 + jl + 16 * jj];
#pragma unroll
        for (int ii = 0; ii < 8; ii++)
#pragma unroll
            for (int jj = 0; jj < 8; jj++) acc[ii][jj] += av[ii] * bv[jj];
    }
    __syncthreads();
#pragma unroll
    for (int ii = 0; ii < 8; ii++)
#pragma unroll
        for (int jj = 0; jj < 8; jj++)
            Ms[(il + 16 * ii) * 129 + (jl + 16 * jj)] = acc[ii][jj];
    __syncthreads();
    for (int idx = t; idx < 128 * 128; idx += 256) {
        int nl = idx & 127, i = idx >> 7;
        out[(size_t)(b * Cc + i) * Nn + n0 + nl] = Ms[i * 129 + nl] + g_r[b][i];
    }
}

// ------------------------------ launch ---------------------------------------
extern "C" void kernel_launch(void* const* d_in, const int* in_sizes, int n_in,
                              void* d_out, int out_size) {
    (void)in_sizes; (void)n_in; (void)out_size;
    const float* u        = (const float*)d_in[0];
    const float* v        = (const float*)d_in[1];
    const float* offset_w = (const float*)d_in[2];
    const float* offset_b = (const float*)d_in[3];
    const float* dcn_w    = (const float*)d_in[4];
    const float* dcn_b    = (const float*)d_in[5];
    const float* q_w      = (const float*)d_in[6];
    const float* q_b      = (const float*)d_in[7];
    const float* k_w      = (const float*)d_in[8];
    const float* k_b      = (const float*)d_in[9];
    const float* v_w      = (const float*)d_in[10];
    const float* v_b      = (const float*)d_in[11];
    float* out = (float*)d_out;

    const int smem_k1 = (3 * 130 * 32 + OCH * KK9 * 32) * 4;   // 70656
    const int smem_big = 2 * 128 * 129 * 4;                    // 132096
    cudaFuncSetAttribute(k1_offset, cudaFuncAttributeMaxDynamicSharedMemorySize, smem_k1);
    cudaFuncSetAttribute(k3_deform, cudaFuncAttributeMaxDynamicSharedMemorySize, K3_DYN);
    cudaFuncSetAttribute(k4_gpart, cudaFuncAttributeMaxDynamicSharedMemorySize, smem_big);
    cudaFuncSetAttribute(k6_out,   cudaFuncAttributeMaxDynamicSharedMemorySize, smem_big);

    k0_prep<<<(KK9 * Cc * Cc + 255) / 256, 256>>>(dcn_w, offset_w);
    k2_transpose<<<dim3(Nn / 32, Cc / 32, NIMG), dim3(32, 8)>>>(u, v);
    k1_offset<<<dim3(Hh, NIMG), 128, smem_k1>>>(offset_b);
    k3_deform<<<dim3(Nn / 128, NIMG), 512, K3_DYN>>>(dcn_b);
    k4_gpart<<<dim3(NCHUNK, Bb), 256, smem_big>>>();
    k4b_reduce<<<130, 256>>>();
    k5_attn<<<dim3(8, Bb), 256>>>(q_w, q_b, k_w, k_b, v_w, v_b);
    k6_out<<<dim3(Nn / 128, Bb), 256, smem_big>>>(out);
}

// round 5
// speedup vs baseline: 1.6657x; 1.0658x over previous
#include <cuda_runtime.h>
#include <cuda_fp16.h>
#include <math.h>
#include <stdint.h>

#define Hh 128
#define Ww 128
#define Cc 128
#define Nn (Hh*Ww)
#define Bb 2
#define NIMG 4          // img = tensor*2 + batch ; tensor 0 = u, 1 = v
#define KK9 9
#define OCH 18
#define NCHUNK 128

// -------- scratch (static device allocations; no runtime alloc allowed) ------
__device__ float g_xnhwc[NIMG][Nn][Cc];   // inputs transposed to NHWC
__device__ float g_off[NIMG][Nn][OCH];    // offset conv output, per-pixel 18 vals
__device__ float g_xd[NIMG][Nn][Cc];      // deformable conv outputs (NHWC)
__device__ __half g_Wh[KK9][Cc][Cc];      // dcn_w hi-half [kk][co][c]
__device__ __half g_Wl[KK9][Cc][Cc];      // dcn_w lo-half
__device__ float g_Wo[OCH][KK9][Cc];      // offset_w transposed [o][kk][c]
__device__ float g_Gp[Bb][NCHUNK][Cc*Cc]; // Gram partials
__device__ float g_sup[Bb][NCHUNK][Cc];
__device__ float g_svp[Bb][NCHUNK][Cc];
__device__ float g_G[Bb][Cc*Cc];
__device__ float g_su[Bb][Cc];
__device__ float g_sv[Bb][Cc];
__device__ float g_Mt[Bb][Cc*Cc];         // (attn @ Vw)^T  [m][i]
__device__ float g_r[Bb][Cc];             // attn @ vb

// ------------------------------ K0: weight prep ------------------------------
__global__ void k0_prep(const float* __restrict__ dcn_w,
                        const float* __restrict__ offset_w) {
    int idx = blockIdx.x * blockDim.x + threadIdx.x;
    if (idx < KK9 * Cc * Cc) {
        int kk = idx / (Cc * Cc);
        int rem = idx % (Cc * Cc);
        int co = rem >> 7, c = rem & 127;
        float w = dcn_w[(co * Cc + c) * KK9 + kk];
        __half h = __float2half_rn(w);
        __half l = __float2half_rn(w - __half2float(h));
        g_Wh[kk][co][c] = h;
        g_Wl[kk][co][c] = l;
    }
    if (idx < OCH * KK9 * Cc) {
        int o = idx / (KK9 * Cc);
        int rem = idx % (KK9 * Cc);
        int kk = rem / Cc, c = rem % Cc;
        g_Wo[o][kk][c] = offset_w[(o * Cc + c) * KK9 + kk];
    }
}

// ------------------------------ K2: NCHW -> NHWC -----------------------------
__global__ void k2_transpose(const float* __restrict__ u,
                             const float* __restrict__ v) {
    __shared__ float tile[32][33];
    int img = blockIdx.z;
    int t = img >> 1, b = img & 1;
    const float* x = t ? v : u;
    int n0 = blockIdx.x * 32, c0 = blockIdx.y * 32;
    int tx = threadIdx.x, ty = threadIdx.y;
#pragma unroll
    for (int i = 0; i < 32; i += 8)
        tile[ty + i][tx] = x[(size_t)(b * Cc + c0 + ty + i) * Nn + n0 + tx];
    __syncthreads();
#pragma unroll
    for (int i = 0; i < 32; i += 8)
        g_xnhwc[img][n0 + ty + i][c0 + tx] = tile[tx][ty + i];
}

// ------------------------------ K1: offset conv (3x3, 18 out ch) -------------
__global__ void k1_offset(const float* __restrict__ offset_b) {
    extern __shared__ float sm1[];
    float* sx = sm1;                     // 3*130*32
    float* wsm = sm1 + 3 * 130 * 32;     // 18*9*32
    int y = blockIdx.x, img = blockIdx.y, t = threadIdx.x;
    float acc[OCH];
#pragma unroll
    for (int o = 0; o < OCH; o++) acc[o] = 0.f;

    for (int c0 = 0; c0 < Cc; c0 += 32) {
        __syncthreads();
        for (int idx = t; idx < 3 * 130 * 32; idx += 128) {
            int cc = idx & 31;
            int rest = idx >> 5;
            int s = rest % 130, r = rest / 130;
            int ry = y + r - 1, gx = s - 1;
            float vv = 0.f;
            if (ry >= 0 && ry < Hh && gx >= 0 && gx < Ww)
                vv = g_xnhwc[img][ry * Ww + gx][c0 + cc];
            sx[(r * 130 + s) * 32 + cc] = vv;
        }
        for (int idx = t; idx < OCH * KK9 * 32; idx += 128) {
            int cc = idx & 31;
            int rest = idx >> 5;
            int tap = rest % KK9, o = rest / KK9;
            wsm[(o * KK9 + tap) * 32 + cc] = g_Wo[o][tap][c0 + cc];
        }
        __syncthreads();
        for (int tap = 0; tap < KK9; tap++) {
            int di = tap / 3, dj = tap % 3;
            const float4* xrow = (const float4*)&sx[((di * 130) + t + dj) * 32];
            for (int c4 = 0; c4 < 8; c4++) {
                float4 xv = xrow[c4];
#pragma unroll
                for (int o = 0; o < OCH; o++) {
                    float4 w4 = *(const float4*)&wsm[(o * KK9 + tap) * 32 + c4 * 4];
                    acc[o] += w4.x * xv.x + w4.y * xv.y + w4.z * xv.z + w4.w * xv.w;
                }
            }
        }
    }
    int n = y * Ww + t;
#pragma unroll
    for (int o = 0; o < OCH; o++)
        g_off[img][n][o] = acc[o] + offset_b[o];
}

// ------------------------------ K3: deformable conv via mma.sync fp16x3 ------
// Block: 128 px x 128 co, 512 threads (16 warps, m32 x n32 tiles).
// ldmatrix.x4 fragment loads; gather uses float4 LDG; B weights streamed via
// cp.async double-buffered across taps.
#define PA 68                       // u32 row pitch (272 bytes)
#define MATB (128 * PA * 4)         // 34816 bytes per half-matrix
#define OFF_ALO  MATB
#define OFF_B0   (2 * MATB)         // buffer0: hi at +0, lo at +MATB
#define OFF_OFS  (6 * MATB)         // int4[128]
#define OFF_WTS  (6 * MATB + 2048)  // float4[128]
#define K3_DYN   (6 * MATB + 4096)  // 212992

__device__ __forceinline__ void mma16816(float* d, uint32_t a0, uint32_t a1,
                                         uint32_t a2, uint32_t a3,
                                         uint32_t b0, uint32_t b1) {
    asm volatile(
        "mma.sync.aligned.m16n8k16.row.col.f32.f16.f16.f32 "
        "{%0,%1,%2,%3}, {%4,%5,%6,%7}, {%8,%9}, {%0,%1,%2,%3};"
        : "+f"(d[0]), "+f"(d[1]), "+f"(d[2]), "+f"(d[3])
        : "r"(a0), "r"(a1), "r"(a2), "r"(a3), "r"(b0), "r"(b1));
}
__device__ __forceinline__ uint32_t smem_u32(const void* p) {
    uint32_t a;
    asm("{ .reg .u64 t; cvta.to.shared.u64 t, %1; cvt.u32.u64 %0, t; }" : "=r"(a) : "l"(p));
    return a;
}
__device__ __forceinline__ void ldm4(uint32_t* r, uint32_t addr) {
    asm volatile("ldmatrix.sync.aligned.m8n8.x4.shared.b16 {%0,%1,%2,%3}, [%4];"
                 : "=r"(r[0]), "=r"(r[1]), "=r"(r[2]), "=r"(r[3]) : "r"(addr));
}
__device__ __forceinline__ void cp16(uint32_t s, const void* g) {
    asm volatile("cp.async.cg.shared.global [%0], [%1], 16;" :: "r"(s), "l"(g));
}

// prefetch one tap's B (hi+lo) into buffer buf; 8 chunks of 16B per thread
__device__ __forceinline__ void prefetch_B(uint32_t sb, int buf, int kk, int t) {
    uint32_t base = sb + OFF_B0 + buf * (2 * MATB);
#pragma unroll
    for (int j = 0; j < 8; j++) {
        int chunk = t + 512 * j;              // 0..4095
        int lo = chunk >> 11;                 // 0: hi, 1: lo
        int cc = chunk & 2047;
        int row = cc >> 4, ch16 = cc & 15;
        const __half* gsrc = lo ? &g_Wl[kk][row][ch16 * 8] : &g_Wh[kk][row][ch16 * 8];
        cp16(base + lo * MATB + (row * PA + ch16 * 4) * 4, gsrc);
    }
    asm volatile("cp.async.commit_group;" ::: "memory");
}

__global__ void __launch_bounds__(512, 1) k3_deform(const float* __restrict__ dcn_b) {
    extern __shared__ char B[];
    uint32_t sb = smem_u32(B);
    uint32_t* A32h = (uint32_t*)B;
    uint32_t* A32l = (uint32_t*)(B + OFF_ALO);
    int4*   s_ofs = (int4*)(B + OFF_OFS);
    float4* s_w   = (float4*)(B + OFF_WTS);

    int t = threadIdx.x, lane = t & 31, wid = t >> 5;
    int img = blockIdx.y, n0 = blockIdx.x * 128;
    const float* X = &g_xnhwc[img][0][0];

    float acc[2][4][4];
#pragma unroll
    for (int mt = 0; mt < 2; mt++)
#pragma unroll
        for (int nt = 0; nt < 4; nt++)
#pragma unroll
            for (int f = 0; f < 4; f++) acc[mt][nt][f] = 0.f;

    int cq = t & 31, pxg = t >> 5;           // channel quad 0..31, px group 0..15
    int c = cq * 4;
    int wm = wid >> 2, wn = wid & 3;         // warp tile coords (4 x 4), m32 x n32

    // ldmatrix lane addresses (272-byte row pitch -> conflict-free)
    uint32_t arow = (lane & 7) + ((lane >> 3) & 1) * 8;
    uint32_t acolB = ((lane >> 4) & 1) * 16;
    uint32_t aAddr0 = sb + (wm * 32 + arow) * 272 + acolB;          // mt=0, hi
    uint32_t brow = (lane & 7) + ((lane >> 4) & 1) * 8;
    uint32_t bcolB = ((lane >> 3) & 1) * 16;
    uint32_t bOff = (wn * 32 + brow) * 272 + bcolB;                 // within matrix

    prefetch_B(sb, 0, 0, t);

    for (int kk = 0; kk < KK9; kk++) {
        __syncthreads();                      // previous tap's mma reads done
        int buf = kk & 1;
        if (kk < KK9 - 1) prefetch_B(sb, buf ^ 1, kk + 1, t);

        if (t < 128) {
            int n = n0 + t;
            float dy = g_off[img][n][kk * 2 + 0];
            float dx = g_off[img][n][kk * 2 + 1];
            float py  = (float)((n >> 7) + kk / 3 - 1) + dy;
            float pxf = (float)((n & 127) + kk % 3 - 1) + dx;
            float y0f = floorf(py), x0f = floorf(pxf);
            int y0 = (int)y0f, x0 = (int)x0f;
            float wy = py - y0f, wx = pxf - x0f;
            int y1 = y0 + 1, x1 = x0 + 1;
            bool vy0 = (unsigned)y0 < (unsigned)Hh, vy1 = (unsigned)y1 < (unsigned)Hh;
            bool vx0 = (unsigned)x0 < (unsigned)Ww, vx1 = (unsigned)x1 < (unsigned)Ww;
            int yc0 = min(max(y0, 0), Hh - 1), yc1 = min(max(y1, 0), Hh - 1);
            int xc0 = min(max(x0, 0), Ww - 1), xc1 = min(max(x1, 0), Ww - 1);
            s_ofs[t] = make_int4((yc0 * Ww + xc0) * Cc, (yc0 * Ww + xc1) * Cc,
                                 (yc1 * Ww + xc0) * Cc, (yc1 * Ww + xc1) * Cc);
            s_w[t] = make_float4(vy0 && vx0 ? (1.f - wy) * (1.f - wx) : 0.f,
                                 vy0 && vx1 ? (1.f - wy) * wx : 0.f,
                                 vy1 && vx0 ? wy * (1.f - wx) : 0.f,
                                 vy1 && vx1 ? wy * wx : 0.f);
        }
        __syncthreads();

        // ---- gather A: samples [128 px][128 ch], float4 loads, split hi/lo ----
#pragma unroll 4
        for (int i = 0; i < 8; i++) {
            int px = pxg + i * 16;
            int4  o = s_ofs[px];
            float4 w = s_w[px];
            float4 v0 = *(const float4*)(X + o.x + c);
            float4 v1 = *(const float4*)(X + o.y + c);
            float4 v2 = *(const float4*)(X + o.z + c);
            float4 v3 = *(const float4*)(X + o.w + c);
            float s0 = w.x * v0.x + w.y * v1.x + w.z * v2.x + w.w * v3.x;
            float s1 = w.x * v0.y + w.y * v1.y + w.z * v2.y + w.w * v3.y;
            float s2 = w.x * v0.z + w.y * v1.z + w.z * v2.z + w.w * v3.z;
            float s3 = w.x * v0.w + w.y * v1.w + w.z * v2.w + w.w * v3.w;
            half2 h01 = __floats2half2_rn(s0, s1);
            half2 h23 = __floats2half2_rn(s2, s3);
            float2 f01 = __half22float2(h01), f23 = __half22float2(h23);
            half2 l01 = __floats2half2_rn(s0 - f01.x, s1 - f01.y);
            half2 l23 = __floats2half2_rn(s2 - f23.x, s3 - f23.y);
            *(uint2*)&A32h[px * PA + cq * 2] =
                make_uint2(*(uint32_t*)&h01, *(uint32_t*)&h23);
            *(uint2*)&A32l[px * PA + cq * 2] =
                make_uint2(*(uint32_t*)&l01, *(uint32_t*)&l23);
        }
        if (kk < KK9 - 1)
            asm volatile("cp.async.wait_group 1;" ::: "memory");
        else
            asm volatile("cp.async.wait_group 0;" ::: "memory");
        __syncthreads();

        uint32_t bh_base = sb + OFF_B0 + buf * (2 * MATB) + bOff;
        uint32_t bl_base = bh_base + MATB;

        // ---- mma: 8 k16-steps x 3 passes, ldmatrix fragment loads ----
#pragma unroll
        for (int kt = 0; kt < 8; kt++) {
            uint32_t kB = kt * 32;
            uint32_t ah[2][4], al[2][4], bh[2][4], bl[2][4];
            ldm4(ah[0], aAddr0 + kB);
            ldm4(ah[1], aAddr0 + 16 * 272 + kB);
            ldm4(al[0], aAddr0 + OFF_ALO + kB);
            ldm4(al[1], aAddr0 + OFF_ALO + 16 * 272 + kB);
            ldm4(bh[0], bh_base + kB);
            ldm4(bh[1], bh_base + 16 * 272 + kB);
            ldm4(bl[0], bl_base + kB);
            ldm4(bl[1], bl_base + 16 * 272 + kB);
#pragma unroll
            for (int ntq = 0; ntq < 2; ntq++) {
#pragma unroll
                for (int sub = 0; sub < 2; sub++) {
                    int nt = ntq * 2 + sub;
                    uint32_t b0h = bh[ntq][sub * 2], b1h = bh[ntq][sub * 2 + 1];
                    uint32_t b0l = bl[ntq][sub * 2], b1l = bl[ntq][sub * 2 + 1];
#pragma unroll
                    for (int mt = 0; mt < 2; mt++) {
                        mma16816(acc[mt][nt], ah[mt][0], ah[mt][1], ah[mt][2], ah[mt][3], b0h, b1h);
                        mma16816(acc[mt][nt], al[mt][0], al[mt][1], al[mt][2], al[mt][3], b0h, b1h);
                        mma16816(acc[mt][nt], ah[mt][0], ah[mt][1], ah[mt][2], ah[mt][3], b0l, b1l);
                    }
                }
            }
        }
    }

    // ---- epilogue: bias + direct store ----
#pragma unroll
    for (int mt = 0; mt < 2; mt++) {
        int r0 = wm * 32 + mt * 16 + (lane >> 2);
#pragma unroll
        for (int nt = 0; nt < 4; nt++) {
            int col = wn * 32 + nt * 8 + (lane & 3) * 2;
            float2 bias = *(const float2*)(dcn_b + col);
            float2 o0 = make_float2(acc[mt][nt][0] + bias.x, acc[mt][nt][1] + bias.y);
            float2 o1 = make_float2(acc[mt][nt][2] + bias.x, acc[mt][nt][3] + bias.y);
            *(float2*)&g_xd[img][n0 + r0][col] = o0;
            *(float2*)&g_xd[img][n0 + r0 + 8][col] = o1;
        }
    }
}

// ------------------------------ K4: Gram partials G = Ud^T Vd ----------------
// 32-row subtiles: 33KB smem -> ~6 blocks/SM.
__global__ void k4_gpart() {
    __shared__ float Us[32][129];
    __shared__ float Vs[32][129];
    int b = blockIdx.y, chunk = blockIdx.x;
    int n0 = chunk * 128, t = threadIdx.x;
    int il = t & 15, jl = t >> 4;

    float acc[8][8];
#pragma unroll
    for (int ii = 0; ii < 8; ii++)
#pragma unroll
        for (int jj = 0; jj < 8; jj++) acc[ii][jj] = 0.f;
    float colsum = 0.f;

    for (int s = 0; s < 4; s++) {
        __syncthreads();
        for (int idx = t; idx < 32 * 128; idx += 256) {
            int cc = idx & 127, nl = idx >> 7;
            Us[nl][cc] = g_xd[b][n0 + s * 32 + nl][cc];
            Vs[nl][cc] = g_xd[2 + b][n0 + s * 32 + nl][cc];
        }
        __syncthreads();
#pragma unroll 4
        for (int nl = 0; nl < 32; nl++) {
            float av[8], bv[8];
#pragma unroll
            for (int ii = 0; ii < 8; ii++) av[ii] = Us[nl][il + 16 * ii];
#pragma unroll
            for (int jj = 0; jj < 8; jj++) bv[jj] = Vs[nl][jl + 16 * jj];
#pragma unroll
            for (int ii = 0; ii < 8; ii++)
#pragma unroll
                for (int jj = 0; jj < 8; jj++) acc[ii][jj] += av[ii] * bv[jj];
        }
        if (t < 128) {
            for (int nl = 0; nl < 32; nl++) colsum += Us[nl][t];
        } else {
            int cc = t - 128;
            for (int nl = 0; nl < 32; nl++) colsum += Vs[nl][cc];
        }
    }
    if (t < 128) g_sup[b][chunk][t] = colsum;
    else         g_svp[b][chunk][t - 128] = colsum;

    // staged coalesced output, 4 passes of 32 rows
    for (int g = 0; g < 4; g++) {
        __syncthreads();
#pragma unroll
        for (int jj = 0; jj < 8; jj++) {
            Us[il][jl + 16 * jj]      = acc[2 * g][jj];
            Us[16 + il][jl + 16 * jj] = acc[2 * g + 1][jj];
        }
        __syncthreads();
        for (int idx = t; idx < 32 * 128; idx += 256) {
            int j = idx & 127, r = idx >> 7;
            g_Gp[b][chunk][(32 * g + r) * 128 + j] = Us[r][j];
        }
    }
}

// ------------------------------ K4b: reduce partials -------------------------
__global__ void k4b_reduce() {
    int idx = blockIdx.x * 256 + threadIdx.x;
    if (idx < Bb * Cc * Cc) {
        int b = idx >> 14;
        int rem = idx & (Cc * Cc - 1);
        float s = 0.f;
        for (int ch = 0; ch < NCHUNK; ch++) s += g_Gp[b][ch][rem];
        g_G[b][rem] = s;
    } else {
        int k = idx - Bb * Cc * Cc;
        if (k < 2 * Bb * Cc) {
            int sel = k >> 8;
            int b = (k >> 7) & 1;
            int c = k & 127;
            float s = 0.f;
            if (sel) { for (int ch = 0; ch < NCHUNK; ch++) s += g_svp[b][ch][c]; g_sv[b][c] = s; }
            else     { for (int ch = 0; ch < NCHUNK; ch++) s += g_sup[b][ch][c]; g_su[b][c] = s; }
        }
    }
}

// ------------------------------ K5: tiny attention math ----------------------
__global__ void k5_attn(const float* __restrict__ q_w, const float* __restrict__ q_b,
                        const float* __restrict__ k_w, const float* __restrict__ k_b,
                        const float* __restrict__ v_w, const float* __restrict__ v_b) {
    __shared__ float P[16][128];
    __shared__ float L[16][128];
    __shared__ float ksv[128];
    __shared__ float qsu[16];
    int b = blockIdx.y;
    int i0 = blockIdx.x * 16;
    int t = threadIdx.x;

    if (t < 128) {
        float s = 0.f;
        for (int a = 0; a < 128; a++) s += k_w[t * 128 + a] * g_sv[b][a];
        ksv[t] = s;
    } else if (t < 144) {
        int i = i0 + (t - 128);
        float s = 0.f;
        for (int a = 0; a < 128; a++) s += q_w[i * 128 + a] * g_su[b][a];
        qsu[t - 128] = s;
    }
    __syncthreads();

    for (int idx = t; idx < 16 * 128; idx += 256) {
        int a = idx & 127, ii = idx >> 7;
        int i = i0 + ii;
        float s = 0.f;
        for (int m = 0; m < 128; m++) s += q_w[i * 128 + m] * g_G[b][m * 128 + a];
        P[ii][a] = s;
    }
    __syncthreads();

    const float scale = 0.088388347648318447f; // 128^-0.5
    for (int idx = t; idx < 16 * 128; idx += 256) {
        int j = idx & 127, ii = idx >> 7;
        int i = i0 + ii;
        float s = 0.f;
        for (int a = 0; a < 128; a++) s += P[ii][a] * k_w[j * 128 + a];
        s += qsu[ii] * k_b[j] + q_b[i] * ksv[j] + (float)Nn * q_b[i] * k_b[j];
        L[ii][j] = s * scale;
    }
    __syncthreads();

    if (t < 16) {
        float m = -1e30f;
        for (int j = 0; j < 128; j++) m = fmaxf(m, L[t][j]);
        float s = 0.f;
        for (int j = 0; j < 128; j++) { float e = expf(L[t][j] - m); L[t][j] = e; s += e; }
        float inv = 1.f / s;
        for (int j = 0; j < 128; j++) L[t][j] *= inv;
    }
    __syncthreads();

    for (int idx = t; idx < 16 * 128; idx += 256) {
        int m = idx & 127, ii = idx >> 7;
        float s = 0.f;
        for (int j = 0; j < 128; j++) s += L[ii][j] * v_w[j * 128 + m];
        g_Mt[b][m * 128 + (i0 + ii)] = s;
    }
    if (t < 16) {
        float s = 0.f;
        for (int j = 0; j < 128; j++) s += L[t][j] * v_b[j];
        g_r[b][i0 + t] = s;
    }
}

// ------------------------------ K6: out = M @ Vd^T + r -----------------------
// 32-row subtiles over m; coalesced loads via g_Mt; staged coalesced writes.
__global__ void k6_out(float* __restrict__ out) {
    __shared__ float Ms[32][129];
    __shared__ float Vs[32][129];
    int b = blockIdx.y, n0 = blockIdx.x * 128, t = threadIdx.x;
    int il = t & 15, jl = t >> 4;

    float acc[8][8];
#pragma unroll
    for (int ii = 0; ii < 8; ii++)
#pragma unroll
        for (int jj = 0; jj < 8; jj++) acc[ii][jj] = 0.f;

    for (int s = 0; s < 4; s++) {
        __syncthreads();
        for (int idx = t; idx < 32 * 128; idx += 256) {
            int i = idx & 127, mm = idx >> 7;
            Ms[mm][i] = g_Mt[b][(s * 32 + mm) * 128 + i];
        }
        for (int idx = t; idx < 32 * 128; idx += 256) {
            int mmr = idx & 31, nl = idx >> 5;
            Vs[mmr][nl] = g_xd[2 + b][n0 + nl][s * 32 + mmr];
        }
        __syncthreads();
#pragma unroll 4
        for (int mm = 0; mm < 32; mm++) {
            float av[8], bv[8];
#pragma unroll
            for (int ii = 0; ii < 8; ii++) av[ii] = Ms[mm][il + 16 * ii];
#pragma unroll
            for (int jj = 0; jj < 8; jj++) bv[jj] = Vs[mm][jl + 16 * jj];
#pragma unroll
            for (int ii = 0; ii < 8; ii++)
#pragma unroll
                for (int jj = 0; jj < 8; jj++) acc[ii][jj] += av[ii] * bv[jj];
        }
    }

    for (int g = 0; g < 4; g++) {
        __syncthreads();
#pragma unroll
        for (int jj = 0; jj < 8; jj++) {
            Ms[il][jl + 16 * jj]      = acc[2 * g][jj];
            Ms[16 + il][jl + 16 * jj] = acc[2 * g + 1][jj];
        }
        __syncthreads();
        for (int idx = t; idx < 32 * 128; idx += 256) {
            int j = idx & 127, r = idx >> 7;
            int i = 32 * g + r;
            out[(size_t)(b * Cc + i) * Nn + n0 + j] = Ms[r][j] + g_r[b][i];
        }
    }
}

// ------------------------------ launch ---------------------------------------
extern "C" void kernel_launch(void* const* d_in, const int* in_sizes, int n_in,
                              void* d_out, int out_size) {
    (void)in_sizes; (void)n_in; (void)out_size;
    const float* u        = (const float*)d_in[0];
    const float* v        = (const float*)d_in[1];
    const float* offset_w = (const float*)d_in[2];
    const float* offset_b = (const float*)d_in[3];
    const float* dcn_w    = (const float*)d_in[4];
    const float* dcn_b    = (const float*)d_in[5];
    const float* q_w      = (const float*)d_in[6];
    const float* q_b      = (const float*)d_in[7];
    const float* k_w      = (const float*)d_in[8];
    const float* k_b      = (const float*)d_in[9];
    const float* v_w      = (const float*)d_in[10];
    const float* v_b      = (const float*)d_in[11];
    float* out = (float*)d_out;

    const int smem_k1 = (3 * 130 * 32 + OCH * KK9 * 32) * 4;   // 70656
    cudaFuncSetAttribute(k1_offset, cudaFuncAttributeMaxDynamicSharedMemorySize, smem_k1);
    cudaFuncSetAttribute(k3_deform, cudaFuncAttributeMaxDynamicSharedMemorySize, K3_DYN);

    k0_prep<<<(KK9 * Cc * Cc + 255) / 256, 256>>>(dcn_w, offset_w);
    k2_transpose<<<dim3(Nn / 32, Cc / 32, NIMG), dim3(32, 8)>>>(u, v);
    k1_offset<<<dim3(Hh, NIMG), 128, smem_k1>>>(offset_b);
    k3_deform<<<dim3(Nn / 128, NIMG), 512, K3_DYN>>>(dcn_b);
    k4_gpart<<<dim3(NCHUNK, Bb), 256>>>();
    k4b_reduce<<<130, 256>>>();
    k5_attn<<<dim3(8, Bb), 256>>>(q_w, q_b, k_w, k_b, v_w, v_b);
    k6_out<<<dim3(Nn / 128, Bb), 256>>>(out);
}

// round 6
// speedup vs baseline: 2.0159x; 1.2103x over previous
#include <cuda_runtime.h>
#include <cuda_fp16.h>
#include <math.h>
#include <stdint.h>

#define Hh 128
#define Ww 128
#define Cc 128
#define Nn (Hh*Ww)
#define Bb 2
#define NIMG 4          // img = tensor*2 + batch ; tensor 0 = u, 1 = v
#define KK9 9
#define OCH 18
#define NCHUNK 128

// -------- scratch (static device allocations; no runtime alloc allowed) ------
__device__ float g_xnhwc[NIMG][Nn][Cc];   // inputs transposed to NHWC
__device__ float g_off[NIMG][Nn][OCH];    // offset conv output, per-pixel 18 vals
__device__ float g_xd[NIMG][Nn][Cc];      // deformable conv outputs (NHWC)
__device__ __half g_Wh[KK9][Cc][Cc];      // dcn_w hi-half [kk][co][c]
__device__ __half g_Wl[KK9][Cc][Cc];      // dcn_w lo-half
__device__ float g_Wo[OCH][KK9][Cc];      // offset_w transposed [o][kk][c]
__device__ float g_Gp[Bb][NCHUNK][Cc*Cc]; // Gram partials
__device__ float g_sup[Bb][NCHUNK][Cc];
__device__ float g_svp[Bb][NCHUNK][Cc];
__device__ float g_G[Bb][Cc*Cc];
__device__ float g_su[Bb][Cc];
__device__ float g_sv[Bb][Cc];
__device__ float g_Mt[Bb][Cc*Cc];         // (attn @ Vw)^T  [m][i]
__device__ float g_r[Bb][Cc];             // attn @ vb

// ------------------------------ K0: weight prep ------------------------------
__global__ void k0_prep(const float* __restrict__ dcn_w,
                        const float* __restrict__ offset_w) {
    int idx = blockIdx.x * blockDim.x + threadIdx.x;
    if (idx < KK9 * Cc * Cc) {
        int kk = idx / (Cc * Cc);
        int rem = idx % (Cc * Cc);
        int co = rem >> 7, c = rem & 127;
        float w = dcn_w[(co * Cc + c) * KK9 + kk];
        __half h = __float2half_rn(w);
        __half l = __float2half_rn(w - __half2float(h));
        g_Wh[kk][co][c] = h;
        g_Wl[kk][co][c] = l;
    }
    if (idx < OCH * KK9 * Cc) {
        int o = idx / (KK9 * Cc);
        int rem = idx % (KK9 * Cc);
        int kk = rem / Cc, c = rem % Cc;
        g_Wo[o][kk][c] = offset_w[(o * Cc + c) * KK9 + kk];
    }
}

// ------------------------------ K2: NCHW -> NHWC -----------------------------
__global__ void k2_transpose(const float* __restrict__ u,
                             const float* __restrict__ v) {
    __shared__ float tile[32][33];
    int img = blockIdx.z;
    int t = img >> 1, b = img & 1;
    const float* x = t ? v : u;
    int n0 = blockIdx.x * 32, c0 = blockIdx.y * 32;
    int tx = threadIdx.x, ty = threadIdx.y;
#pragma unroll
    for (int i = 0; i < 32; i += 8)
        tile[ty + i][tx] = x[(size_t)(b * Cc + c0 + ty + i) * Nn + n0 + tx];
    __syncthreads();
#pragma unroll
    for (int i = 0; i < 32; i += 8)
        g_xnhwc[img][n0 + ty + i][c0 + tx] = tile[tx][ty + i];
}

// ------------------------------ K1: offset conv (3x3, 18 out ch) -------------
__global__ void k1_offset(const float* __restrict__ offset_b) {
    extern __shared__ float sm1[];
    float* sx = sm1;                     // 3*130*32
    float* wsm = sm1 + 3 * 130 * 32;     // 18*9*32
    int y = blockIdx.x, img = blockIdx.y, t = threadIdx.x;
    float acc[OCH];
#pragma unroll
    for (int o = 0; o < OCH; o++) acc[o] = 0.f;

    for (int c0 = 0; c0 < Cc; c0 += 32) {
        __syncthreads();
        for (int idx = t; idx < 3 * 130 * 32; idx += 128) {
            int cc = idx & 31;
            int rest = idx >> 5;
            int s = rest % 130, r = rest / 130;
            int ry = y + r - 1, gx = s - 1;
            float vv = 0.f;
            if (ry >= 0 && ry < Hh && gx >= 0 && gx < Ww)
                vv = g_xnhwc[img][ry * Ww + gx][c0 + cc];
            sx[(r * 130 + s) * 32 + cc] = vv;
        }
        for (int idx = t; idx < OCH * KK9 * 32; idx += 128) {
            int cc = idx & 31;
            int rest = idx >> 5;
            int tap = rest % KK9, o = rest / KK9;
            wsm[(o * KK9 + tap) * 32 + cc] = g_Wo[o][tap][c0 + cc];
        }
        __syncthreads();
        for (int tap = 0; tap < KK9; tap++) {
            int di = tap / 3, dj = tap % 3;
            const float4* xrow = (const float4*)&sx[((di * 130) + t + dj) * 32];
            for (int c4 = 0; c4 < 8; c4++) {
                float4 xv = xrow[c4];
#pragma unroll
                for (int o = 0; o < OCH; o++) {
                    float4 w4 = *(const float4*)&wsm[(o * KK9 + tap) * 32 + c4 * 4];
                    acc[o] += w4.x * xv.x + w4.y * xv.y + w4.z * xv.z + w4.w * xv.w;
                }
            }
        }
    }
    int n = y * Ww + t;
#pragma unroll
    for (int o = 0; o < OCH; o++)
        g_off[img][n][o] = acc[o] + offset_b[o];
}

// ------------------------------ K3: deformable conv via mma.sync fp16x3 ------
// Block: 64 px x 128 co, 256 threads (8 warps, m16 x n64 tiles), 2 blocks/SM.
// A gathered+split per tap; B streamed via cp.async (single buffer, prefetch
// at tap start hidden behind gather). Cross-block overlap hides phase stalls.
#define PA 68                       // u32 row pitch (272 bytes)
#define MATB (128 * PA * 4)         // 34816 bytes (B half-matrix)
#define MATA (64 * PA * 4)          // 17408 bytes (A half-matrix)
#define OFF_ALO  MATA
#define OFF_BHI  (2 * MATA)
#define OFF_BLO  (2 * MATA + MATB)
#define OFF_OFS  (2 * MATA + 2 * MATB)          // int4[64]
#define OFF_WTS  (2 * MATA + 2 * MATB + 1024)   // float4[64]
#define K3_DYN   (2 * MATA + 2 * MATB + 2048)   // 106496

__device__ __forceinline__ void mma16816(float* d, uint32_t a0, uint32_t a1,
                                         uint32_t a2, uint32_t a3,
                                         uint32_t b0, uint32_t b1) {
    asm volatile(
        "mma.sync.aligned.m16n8k16.row.col.f32.f16.f16.f32 "
        "{%0,%1,%2,%3}, {%4,%5,%6,%7}, {%8,%9}, {%0,%1,%2,%3};"
        : "+f"(d[0]), "+f"(d[1]), "+f"(d[2]), "+f"(d[3])
        : "r"(a0), "r"(a1), "r"(a2), "r"(a3), "r"(b0), "r"(b1));
}
__device__ __forceinline__ uint32_t smem_u32(const void* p) {
    uint32_t a;
    asm("{ .reg .u64 t; cvta.to.shared.u64 t, %1; cvt.u32.u64 %0, t; }" : "=r"(a) : "l"(p));
    return a;
}
__device__ __forceinline__ void ldm4(uint32_t* r, uint32_t addr) {
    asm volatile("ldmatrix.sync.aligned.m8n8.x4.shared.b16 {%0,%1,%2,%3}, [%4];"
                 : "=r"(r[0]), "=r"(r[1]), "=r"(r[2]), "=r"(r[3]) : "r"(addr));
}
__device__ __forceinline__ void cp16(uint32_t s, const void* g) {
    asm volatile("cp.async.cg.shared.global [%0], [%1], 16;" :: "r"(s), "l"(g));
}

// prefetch one tap's B (hi+lo); 16 chunks of 16B per thread (256 threads)
__device__ __forceinline__ void prefetch_B(uint32_t sb, int kk, int t) {
    uint32_t base = sb + OFF_BHI;
#pragma unroll
    for (int j = 0; j < 16; j++) {
        int chunk = t + 256 * j;              // 0..4095
        int lo = chunk >> 11;                 // 0: hi, 1: lo
        int cc = chunk & 2047;
        int row = cc >> 4, ch16 = cc & 15;
        const __half* gsrc = lo ? &g_Wl[kk][row][ch16 * 8] : &g_Wh[kk][row][ch16 * 8];
        cp16(base + lo * MATB + (row * PA + ch16 * 4) * 4, gsrc);
    }
    asm volatile("cp.async.commit_group;" ::: "memory");
}

__global__ void __launch_bounds__(256, 2) k3_deform(const float* __restrict__ dcn_b) {
    extern __shared__ char B[];
    uint32_t sb = smem_u32(B);
    uint32_t* A32h = (uint32_t*)B;
    uint32_t* A32l = (uint32_t*)(B + OFF_ALO);
    int4*   s_ofs = (int4*)(B + OFF_OFS);
    float4* s_w   = (float4*)(B + OFF_WTS);

    int t = threadIdx.x, lane = t & 31, wid = t >> 5;
    int img = blockIdx.y, n0 = blockIdx.x * 64;
    const float* X = &g_xnhwc[img][0][0];

    float acc[8][4];
#pragma unroll
    for (int nt = 0; nt < 8; nt++)
#pragma unroll
        for (int f = 0; f < 4; f++) acc[nt][f] = 0.f;

    int cq = t & 31, pxg = t >> 5;           // channel quad 0..31, px group 0..7
    int c = cq * 4;
    int wm = wid & 3, wn = wid >> 2;         // warp tiles: 4 x m16, 2 x n64

    // ldmatrix lane addresses (272-byte row pitch -> conflict-free)
    uint32_t arow = (lane & 7) + ((lane >> 3) & 1) * 8;
    uint32_t acolB = ((lane >> 4) & 1) * 16;
    uint32_t aAddr0 = sb + (wm * 16 + arow) * 272 + acolB;
    uint32_t brow = (lane & 7) + ((lane >> 4) & 1) * 8;
    uint32_t bcolB = ((lane >> 3) & 1) * 16;
    uint32_t bOff = (wn * 64 + brow) * 272 + bcolB;

    for (int kk = 0; kk < KK9; kk++) {
        __syncthreads();                      // prev tap's mma done (A and B free)
        prefetch_B(sb, kk, t);

        if (t < 64) {
            int n = n0 + t;
            float dy = g_off[img][n][kk * 2 + 0];
            float dx = g_off[img][n][kk * 2 + 1];
            float py  = (float)((n >> 7) + kk / 3 - 1) + dy;
            float pxf = (float)((n & 127) + kk % 3 - 1) + dx;
            float y0f = floorf(py), x0f = floorf(pxf);
            int y0 = (int)y0f, x0 = (int)x0f;
            float wy = py - y0f, wx = pxf - x0f;
            int y1 = y0 + 1, x1 = x0 + 1;
            bool vy0 = (unsigned)y0 < (unsigned)Hh, vy1 = (unsigned)y1 < (unsigned)Hh;
            bool vx0 = (unsigned)x0 < (unsigned)Ww, vx1 = (unsigned)x1 < (unsigned)Ww;
            int yc0 = min(max(y0, 0), Hh - 1), yc1 = min(max(y1, 0), Hh - 1);
            int xc0 = min(max(x0, 0), Ww - 1), xc1 = min(max(x1, 0), Ww - 1);
            s_ofs[t] = make_int4((yc0 * Ww + xc0) * Cc, (yc0 * Ww + xc1) * Cc,
                                 (yc1 * Ww + xc0) * Cc, (yc1 * Ww + xc1) * Cc);
            s_w[t] = make_float4(vy0 && vx0 ? (1.f - wy) * (1.f - wx) : 0.f,
                                 vy0 && vx1 ? (1.f - wy) * wx : 0.f,
                                 vy1 && vx0 ? wy * (1.f - wx) : 0.f,
                                 vy1 && vx1 ? wy * wx : 0.f);
        }
        __syncthreads();

        // ---- gather A: samples [64 px][128 ch], float4 loads, split hi/lo ----
#pragma unroll 4
        for (int i = 0; i < 8; i++) {
            int px = pxg + i * 8;
            int4  o = s_ofs[px];
            float4 w = s_w[px];
            float4 v0 = *(const float4*)(X + o.x + c);
            float4 v1 = *(const float4*)(X + o.y + c);
            float4 v2 = *(const float4*)(X + o.z + c);
            float4 v3 = *(const float4*)(X + o.w + c);
            float s0 = w.x * v0.x + w.y * v1.x + w.z * v2.x + w.w * v3.x;
            float s1 = w.x * v0.y + w.y * v1.y + w.z * v2.y + w.w * v3.y;
            float s2 = w.x * v0.z + w.y * v1.z + w.z * v2.z + w.w * v3.z;
            float s3 = w.x * v0.w + w.y * v1.w + w.z * v2.w + w.w * v3.w;
            half2 h01 = __floats2half2_rn(s0, s1);
            half2 h23 = __floats2half2_rn(s2, s3);
            float2 f01 = __half22float2(h01), f23 = __half22float2(h23);
            half2 l01 = __floats2half2_rn(s0 - f01.x, s1 - f01.y);
            half2 l23 = __floats2half2_rn(s2 - f23.x, s3 - f23.y);
            *(uint2*)&A32h[px * PA + cq * 2] =
                make_uint2(*(uint32_t*)&h01, *(uint32_t*)&h23);
            *(uint2*)&A32l[px * PA + cq * 2] =
                make_uint2(*(uint32_t*)&l01, *(uint32_t*)&l23);
        }
        asm volatile("cp.async.wait_group 0;" ::: "memory");
        __syncthreads();

        uint32_t bh_base = sb + OFF_BHI + bOff;
        uint32_t bl_base = sb + OFF_BLO + bOff;

        // ---- mma: 8 k16-steps x 3 passes, ldmatrix fragment loads ----
#pragma unroll
        for (int kt = 0; kt < 8; kt++) {
            uint32_t kB = kt * 32;
            uint32_t ah[4], al[4], bh[4][4], bl[4][4];
            ldm4(ah, aAddr0 + kB);
            ldm4(al, aAddr0 + OFF_ALO + kB);
#pragma unroll
            for (int ntq = 0; ntq < 4; ntq++) {
                ldm4(bh[ntq], bh_base + ntq * 16 * 272 + kB);
                ldm4(bl[ntq], bl_base + ntq * 16 * 272 + kB);
            }
#pragma unroll
            for (int ntq = 0; ntq < 4; ntq++) {
#pragma unroll
                for (int sub = 0; sub < 2; sub++) {
                    int nt = ntq * 2 + sub;
                    uint32_t b0h = bh[ntq][sub * 2], b1h = bh[ntq][sub * 2 + 1];
                    uint32_t b0l = bl[ntq][sub * 2], b1l = bl[ntq][sub * 2 + 1];
                    mma16816(acc[nt], ah[0], ah[1], ah[2], ah[3], b0h, b1h);
                    mma16816(acc[nt], al[0], al[1], al[2], al[3], b0h, b1h);
                    mma16816(acc[nt], ah[0], ah[1], ah[2], ah[3], b0l, b1l);
                }
            }
        }
    }

    // ---- epilogue: bias + direct store ----
    int r0 = wm * 16 + (lane >> 2);
#pragma unroll
    for (int nt = 0; nt < 8; nt++) {
        int col = wn * 64 + nt * 8 + (lane & 3) * 2;
        float2 bias = *(const float2*)(dcn_b + col);
        float2 o0 = make_float2(acc[nt][0] + bias.x, acc[nt][1] + bias.y);
        float2 o1 = make_float2(acc[nt][2] + bias.x, acc[nt][3] + bias.y);
        *(float2*)&g_xd[img][n0 + r0][col] = o0;
        *(float2*)&g_xd[img][n0 + r0 + 8][col] = o1;
    }
}

// ------------------------------ K4: Gram partials G = Ud^T Vd ----------------
// 32-row subtiles: 33KB smem -> ~6 blocks/SM.
__global__ void k4_gpart() {
    __shared__ float Us[32][129];
    __shared__ float Vs[32][129];
    int b = blockIdx.y, chunk = blockIdx.x;
    int n0 = chunk * 128, t = threadIdx.x;
    int il = t & 15, jl = t >> 4;

    float acc[8][8];
#pragma unroll
    for (int ii = 0; ii < 8; ii++)
#pragma unroll
        for (int jj = 0; jj < 8; jj++) acc[ii][jj] = 0.f;
    float colsum = 0.f;

    for (int s = 0; s < 4; s++) {
        __syncthreads();
        for (int idx = t; idx < 32 * 128; idx += 256) {
            int cc = idx & 127, nl = idx >> 7;
            Us[nl][cc] = g_xd[b][n0 + s * 32 + nl][cc];
            Vs[nl][cc] = g_xd[2 + b][n0 + s * 32 + nl][cc];
        }
        __syncthreads();
#pragma unroll 4
        for (int nl = 0; nl < 32; nl++) {
            float av[8], bv[8];
#pragma unroll
            for (int ii = 0; ii < 8; ii++) av[ii] = Us[nl][il + 16 * ii];
#pragma unroll
            for (int jj = 0; jj < 8; jj++) bv[jj] = Vs[nl][jl + 16 * jj];
#pragma unroll
            for (int ii = 0; ii < 8; ii++)
#pragma unroll
                for (int jj = 0; jj < 8; jj++) acc[ii][jj] += av[ii] * bv[jj];
        }
        if (t < 128) {
            for (int nl = 0; nl < 32; nl++) colsum += Us[nl][t];
        } else {
            int cc = t - 128;
            for (int nl = 0; nl < 32; nl++) colsum += Vs[nl][cc];
        }
    }
    if (t < 128) g_sup[b][chunk][t] = colsum;
    else         g_svp[b][chunk][t - 128] = colsum;

    for (int g = 0; g < 4; g++) {
        __syncthreads();
#pragma unroll
        for (int jj = 0; jj < 8; jj++) {
            Us[il][jl + 16 * jj]      = acc[2 * g][jj];
            Us[16 + il][jl + 16 * jj] = acc[2 * g + 1][jj];
        }
        __syncthreads();
        for (int idx = t; idx < 32 * 128; idx += 256) {
            int j = idx & 127, r = idx >> 7;
            g_Gp[b][chunk][(32 * g + r) * 128 + j] = Us[r][j];
        }
    }
}

// ------------------------------ K4b: reduce partials -------------------------
__global__ void k4b_reduce() {
    int idx = blockIdx.x * 256 + threadIdx.x;
    if (idx < Bb * Cc * Cc) {
        int b = idx >> 14;
        int rem = idx & (Cc * Cc - 1);
        float s = 0.f;
        for (int ch = 0; ch < NCHUNK; ch++) s += g_Gp[b][ch][rem];
        g_G[b][rem] = s;
    } else {
        int k = idx - Bb * Cc * Cc;
        if (k < 2 * Bb * Cc) {
            int sel = k >> 8;
            int b = (k >> 7) & 1;
            int c = k & 127;
            float s = 0.f;
            if (sel) { for (int ch = 0; ch < NCHUNK; ch++) s += g_svp[b][ch][c]; g_sv[b][c] = s; }
            else     { for (int ch = 0; ch < NCHUNK; ch++) s += g_sup[b][ch][c]; g_su[b][c] = s; }
        }
    }
}

// ------------------------------ K5: tiny attention math ----------------------
// grid (32, Bb), 256 threads, 4 attention rows per block; warp-reduced softmax.
__global__ void k5_attn(const float* __restrict__ q_w, const float* __restrict__ q_b,
                        const float* __restrict__ k_w, const float* __restrict__ k_b,
                        const float* __restrict__ v_w, const float* __restrict__ v_b) {
    __shared__ float P[4][128];
    __shared__ float L[4][128];
    __shared__ float ksv[128];
    __shared__ float qsu[4];
    int b = blockIdx.y;
    int i0 = blockIdx.x * 4;
    int t = threadIdx.x;
    int lane = t & 31, wid = t >> 5;

    if (t < 128) {
        float s = 0.f;
        for (int a = 0; a < 128; a++) s += k_w[t * 128 + a] * g_sv[b][a];
        ksv[t] = s;
    } else if (t < 132) {
        int i = i0 + (t - 128);
        float s = 0.f;
        for (int a = 0; a < 128; a++) s += q_w[i * 128 + a] * g_su[b][a];
        qsu[t - 128] = s;
    }
    __syncthreads();

    for (int idx = t; idx < 4 * 128; idx += 256) {
        int a = idx & 127, ii = idx >> 7;
        int i = i0 + ii;
        float s = 0.f;
        for (int m = 0; m < 128; m++) s += q_w[i * 128 + m] * g_G[b][m * 128 + a];
        P[ii][a] = s;
    }
    __syncthreads();

    const float scale = 0.088388347648318447f; // 128^-0.5
    for (int idx = t; idx < 4 * 128; idx += 256) {
        int j = idx & 127, ii = idx >> 7;
        int i = i0 + ii;
        float s = 0.f;
        for (int a = 0; a < 128; a++) s += P[ii][a] * k_w[j * 128 + a];
        s += qsu[ii] * k_b[j] + q_b[i] * ksv[j] + (float)Nn * q_b[i] * k_b[j];
        L[ii][j] = s * scale;
    }
    __syncthreads();

    if (wid < 4) {
        int r = wid;
        float v[4];
        float m = -1e30f;
#pragma unroll
        for (int q = 0; q < 4; q++) { v[q] = L[r][lane + 32 * q]; m = fmaxf(m, v[q]); }
#pragma unroll
        for (int o = 16; o > 0; o >>= 1) m = fmaxf(m, __shfl_xor_sync(0xFFFFFFFFu, m, o));
        float s = 0.f;
#pragma unroll
        for (int q = 0; q < 4; q++) { v[q] = expf(v[q] - m); s += v[q]; }
#pragma unroll
        for (int o = 16; o > 0; o >>= 1) s += __shfl_xor_sync(0xFFFFFFFFu, s, o);
        float inv = 1.f / s;
#pragma unroll
        for (int q = 0; q < 4; q++) L[r][lane + 32 * q] = v[q] * inv;
    }
    __syncthreads();

    for (int idx = t; idx < 4 * 128; idx += 256) {
        int m = idx & 127, ii = idx >> 7;
        float s = 0.f;
        for (int j = 0; j < 128; j++) s += L[ii][j] * v_w[j * 128 + m];
        g_Mt[b][m * 128 + (i0 + ii)] = s;
    }
    if (t < 4) {
        float s = 0.f;
        for (int j = 0; j < 128; j++) s += L[t][j] * v_b[j];
        g_r[b][i0 + t] = s;
    }
}

// ------------------------------ K6: out = M @ Vd^T + r -----------------------
__global__ void k6_out(float* __restrict__ out) {
    __shared__ float Ms[32][129];
    __shared__ float Vs[32][129];
    int b = blockIdx.y, n0 = blockIdx.x * 128, t = threadIdx.x;
    int il = t & 15, jl = t >> 4;

    float acc[8][8];
#pragma unroll
    for (int ii = 0; ii < 8; ii++)
#pragma unroll
        for (int jj = 0; jj < 8; jj++) acc[ii][jj] = 0.f;

    for (int s = 0; s < 4; s++) {
        __syncthreads();
        for (int idx = t; idx < 32 * 128; idx += 256) {
            int i = idx & 127, mm = idx >> 7;
            Ms[mm][i] = g_Mt[b][(s * 32 + mm) * 128 + i];
        }
        for (int idx = t; idx < 32 * 128; idx += 256) {
            int mmr = idx & 31, nl = idx >> 5;
            Vs[mmr][nl] = g_xd[2 + b][n0 + nl][s * 32 + mmr];
        }
        __syncthreads();
#pragma unroll 4
        for (int mm = 0; mm < 32; mm++) {
            float av[8], bv[8];
#pragma unroll
            for (int ii = 0; ii < 8; ii++) av[ii] = Ms[mm][il + 16 * ii];
#pragma unroll
            for (int jj = 0; jj < 8; jj++) bv[jj] = Vs[mm][jl + 16 * jj];
#pragma unroll
            for (int ii = 0; ii < 8; ii++)
#pragma unroll
                for (int jj = 0; jj < 8; jj++) acc[ii][jj] += av[ii] * bv[jj];
        }
    }

    for (int g = 0; g < 4; g++) {
        __syncthreads();
#pragma unroll
        for (int jj = 0; jj < 8; jj++) {
            Ms[il][jl + 16 * jj]      = acc[2 * g][jj];
            Ms[16 + il][jl + 16 * jj] = acc[2 * g + 1][jj];
        }
        __syncthreads();
        for (int idx = t; idx < 32 * 128; idx += 256) {
            int j = idx & 127, r = idx >> 7;
            int i = 32 * g + r;
            out[(size_t)(b * Cc + i) * Nn + n0 + j] = Ms[r][j] + g_r[b][i];
        }
    }
}

// ------------------------------ launch ---------------------------------------
extern "C" void kernel_launch(void* const* d_in, const int* in_sizes, int n_in,
                              void* d_out, int out_size) {
    (void)in_sizes; (void)n_in; (void)out_size;
    const float* u        = (const float*)d_in[0];
    const float* v        = (const float*)d_in[1];
    const float* offset_w = (const float*)d_in[2];
    const float* offset_b = (const float*)d_in[3];
    const float* dcn_w    = (const float*)d_in[4];
    const float* dcn_b    = (const float*)d_in[5];
    const float* q_w      = (const float*)d_in[6];
    const float* q_b      = (const float*)d_in[7];
    const float* k_w      = (const float*)d_in[8];
    const float* k_b      = (const float*)d_in[9];
    const float* v_w      = (const float*)d_in[10];
    const float* v_b      = (const float*)d_in[11];
    float* out = (float*)d_out;

    const int smem_k1 = (3 * 130 * 32 + OCH * KK9 * 32) * 4;   // 70656
    cudaFuncSetAttribute(k1_offset, cudaFuncAttributeMaxDynamicSharedMemorySize, smem_k1);
    cudaFuncSetAttribute(k3_deform, cudaFuncAttributeMaxDynamicSharedMemorySize, K3_DYN);

    k0_prep<<<(KK9 * Cc * Cc + 255) / 256, 256>>>(dcn_w, offset_w);
    k2_transpose<<<dim3(Nn / 32, Cc / 32, NIMG), dim3(32, 8)>>>(u, v);
    k1_offset<<<dim3(Hh, NIMG), 128, smem_k1>>>(offset_b);
    k3_deform<<<dim3(Nn / 64, NIMG), 256, K3_DYN>>>(dcn_b);
    k4_gpart<<<dim3(NCHUNK, Bb), 256>>>();
    k4b_reduce<<<130, 256>>>();
    k5_attn<<<dim3(32, Bb), 256>>>(q_w, q_b, k_w, k_b, v_w, v_b);
    k6_out<<<dim3(Nn / 128, Bb), 256>>>(out);
}

// round 8
// speedup vs baseline: 3.1661x; 1.5706x over previous
#include <cuda_runtime.h>
#include <cuda_fp16.h>
#include <math.h>
#include <stdint.h>

#define Hh 128
#define Ww 128
#define Cc 128
#define Nn (Hh*Ww)
#define Bb 2
#define NIMG 4          // img = tensor*2 + batch ; tensor 0 = u, 1 = v
#define KK9 9
#define OCH 18
#define NCHUNK 128

// -------- scratch (static device allocations; no runtime alloc allowed) ------
__device__ float g_xnhwc[NIMG][Nn][Cc];   // inputs transposed to NHWC (fp32)
__device__ __half g_xh[NIMG][Nn][Cc];     // x hi-half
__device__ __half g_xl[NIMG][Nn][Cc];     // x lo-half
__device__ float g_off[NIMG][Nn][OCH];    // offset conv output, per-pixel 18 vals
__device__ float g_xd[NIMG][Nn][Cc];      // deformable conv outputs (NHWC)
__device__ __half g_Wh[KK9][Cc][Cc];      // dcn_w hi-half [kk][co][c]
__device__ __half g_Wl[KK9][Cc][Cc];      // dcn_w lo-half
__device__ __half g_Woh[KK9][32][Cc];     // offset_w hi [tap][out(pad32)][c]
__device__ __half g_Wol[KK9][32][Cc];     // offset_w lo
__device__ float g_Gp[Bb][NCHUNK][Cc*Cc]; // Gram partials
__device__ float g_sup[Bb][NCHUNK][Cc];
__device__ float g_svp[Bb][NCHUNK][Cc];
__device__ float g_G[Bb][Cc*Cc];
__device__ float g_su[Bb][Cc];
__device__ float g_sv[Bb][Cc];
__device__ float g_Mt[Bb][Cc*Cc];         // (attn @ Vw)^T  [m][i]
__device__ float g_r[Bb][Cc];             // attn @ vb

// ------------------------------ common helpers -------------------------------
__device__ __forceinline__ void mma16816(float* d, uint32_t a0, uint32_t a1,
                                         uint32_t a2, uint32_t a3,
                                         uint32_t b0, uint32_t b1) {
    asm volatile(
        "mma.sync.aligned.m16n8k16.row.col.f32.f16.f16.f32 "
        "{%0,%1,%2,%3}, {%4,%5,%6,%7}, {%8,%9}, {%0,%1,%2,%3};"
        : "+f"(d[0]), "+f"(d[1]), "+f"(d[2]), "+f"(d[3])
        : "r"(a0), "r"(a1), "r"(a2), "r"(a3), "r"(b0), "r"(b1));
}
__device__ __forceinline__ uint32_t smem_u32(const void* p) {
    uint32_t a;
    asm("{ .reg .u64 t; cvta.to.shared.u64 t, %1; cvt.u32.u64 %0, t; }" : "=r"(a) : "l"(p));
    return a;
}
__device__ __forceinline__ void ldm4(uint32_t* r, uint32_t addr) {
    asm volatile("ldmatrix.sync.aligned.m8n8.x4.shared.b16 {%0,%1,%2,%3}, [%4];"
                 : "=r"(r[0]), "=r"(r[1]), "=r"(r[2]), "=r"(r[3]) : "r"(addr));
}
__device__ __forceinline__ void cp16(uint32_t s, const void* g) {
    asm volatile("cp.async.cg.shared.global [%0], [%1], 16;" :: "r"(s), "l"(g));
}

// ------------------------------ K0: weight prep ------------------------------
__global__ void k0_prep(const float* __restrict__ dcn_w,
                        const float* __restrict__ offset_w) {
    int idx = blockIdx.x * blockDim.x + threadIdx.x;
    if (idx < KK9 * Cc * Cc) {
        int kk = idx / (Cc * Cc);
        int rem = idx % (Cc * Cc);
        int co = rem >> 7, c = rem & 127;
        float w = dcn_w[(co * Cc + c) * KK9 + kk];
        __half h = __float2half_rn(w);
        __half l = __float2half_rn(w - __half2float(h));
        g_Wh[kk][co][c] = h;
        g_Wl[kk][co][c] = l;
    }
    if (idx < KK9 * 32 * Cc) {
        int tap = idx / (32 * Cc);
        int rem = idx % (32 * Cc);
        int o = rem >> 7, c = rem & 127;
        float w = (o < OCH) ? offset_w[(o * Cc + c) * KK9 + tap] : 0.f;
        __half h = __float2half_rn(w);
        __half l = __float2half_rn(w - __half2float(h));
        g_Woh[tap][o][c] = h;
        g_Wol[tap][o][c] = l;
    }
}

// ------------------------------ K2: NCHW -> NHWC (+ hi/lo split) -------------
__global__ void k2_transpose(const float* __restrict__ u,
                             const float* __restrict__ v) {
    __shared__ float tile[32][33];
    int img = blockIdx.z;
    int t = img >> 1, b = img & 1;
    const float* x = t ? v : u;
    int n0 = blockIdx.x * 32, c0 = blockIdx.y * 32;
    int tx = threadIdx.x, ty = threadIdx.y;
#pragma unroll
    for (int i = 0; i < 32; i += 8)
        tile[ty + i][tx] = x[(size_t)(b * Cc + c0 + ty + i) * Nn + n0 + tx];
    __syncthreads();
#pragma unroll
    for (int i = 0; i < 32; i += 8) {
        float vv = tile[tx][ty + i];
        int n = n0 + ty + i, c = c0 + tx;
        g_xnhwc[img][n][c] = vv;
        __half h = __float2half_rn(vv);
        g_xh[img][n][c] = h;
        g_xl[img][n][c] = __float2half_rn(vv - __half2float(h));
    }
}

// ------------------------------ K1: offset conv via mma fp16x3 ---------------
// Block = one image row (128 px) x 32 outs (18 real), 256 threads (8 warps,
// m16 each). smem: 3 input rows (halo'd, 32-ch chunk) + per-tap weights.
// Per tap the A tile is a shifted view into the 3-row buffer.
#define XP 80                       // bytes per 32-ch half row (64 data + 16 pad)
#define XHALF (3 * 130 * XP)        // 31200
#define OFF_XL  XHALF
#define OFF_WH  (2 * XHALF)         // 62400
#define WHALF (KK9 * 32 * XP)       // 23040
#define OFF_WL  (OFF_WH + WHALF)
#define K1_DYN  (OFF_WH + 2 * WHALF)  // 108480

__global__ void __launch_bounds__(256, 2) k1_offset(const float* __restrict__ offset_b) {
    extern __shared__ char S[];
    uint32_t sb = smem_u32(S);
    int t = threadIdx.x, lane = t & 31, wid = t >> 5;
    int y = blockIdx.x, img = blockIdx.y;

    float acc[4][4];
#pragma unroll
    for (int nt = 0; nt < 4; nt++)
#pragma unroll
        for (int f = 0; f < 4; f++) acc[nt][f] = 0.f;

    uint32_t arow = (lane & 7) + ((lane >> 3) & 1) * 8;
    uint32_t acolB = ((lane >> 4) & 1) * 16;
    uint32_t brow = (lane & 7) + ((lane >> 4) & 1) * 8;
    uint32_t bcolB = ((lane >> 3) & 1) * 16;
    int wm = wid;                    // 8 warps x m16 = 128 px

    for (int ch = 0; ch < 4; ch++) {
        __syncthreads();             // prev chunk mma done
        // zero x region (halo + OOB rows stay zero)
        for (int i = t * 16; i < 2 * XHALF; i += 256 * 16)
            *(float4*)(S + i) = make_float4(0.f, 0.f, 0.f, 0.f);
        __syncthreads();
        // x rows: 3 rows x 128 px x 4 chunks x 2 halves = 3072 chunks
        // hi occupies chunks [0,1536), lo [1536,3072)
#pragma unroll
        for (int j = 0; j < 12; j++) {
            int idx = t + 256 * j;               // 0..3071
            int sel = (idx >= 1536) ? 1 : 0;     // 0: hi, 1: lo
            int i2 = idx - sel * 1536;           // 0..1535
            int row3 = i2 >> 9;                  // 0..2
            int win = i2 & 511;
            int px = win >> 2, c16 = win & 3;
            int gy = y + row3 - 1;
            if ((unsigned)gy < (unsigned)Hh) {
                const __half* gsrc = sel ? &g_xl[img][gy * Ww + px][ch * 32 + c16 * 8]
                                         : &g_xh[img][gy * Ww + px][ch * 32 + c16 * 8];
                cp16(sb + sel * XHALF + ((row3 * 130) + px + 1) * XP + c16 * 16, gsrc);
            }
        }
        // weights: 9 taps x 32 outs x 4 chunks x 2 halves = 2304 chunks
#pragma unroll
        for (int j = 0; j < 9; j++) {
            int idx = t + 256 * j;               // 0..2303
            int sel = (idx >= 1152) ? 1 : 0;
            int i2 = idx - sel * 1152;           // 0..1151
            int tap = i2 >> 7;
            int win = i2 & 127;
            int o = win >> 2, c16 = win & 3;
            const __half* gsrc = sel ? &g_Wol[tap][o][ch * 32 + c16 * 8]
                                     : &g_Woh[tap][o][ch * 32 + c16 * 8];
            cp16(sb + OFF_WH + sel * WHALF + (tap * 32 + o) * XP + c16 * 16, gsrc);
        }
        asm volatile("cp.async.commit_group;" ::: "memory");
        asm volatile("cp.async.wait_group 0;" ::: "memory");
        __syncthreads();

#pragma unroll
        for (int tap = 0; tap < KK9; tap++) {
            int di = tap / 3, dj = tap % 3;
            uint32_t abase = sb + ((uint32_t)(di * 130 + dj + wm * 16) + arow) * XP + acolB;
            uint32_t bbase = sb + OFF_WH + (tap * 32 + brow) * XP + bcolB;
#pragma unroll
            for (int ks = 0; ks < 2; ks++) {
                uint32_t kB = ks * 32;
                uint32_t ah[4], al[4], bh[2][4], bl[2][4];
                ldm4(ah, abase + kB);
                ldm4(al, abase + XHALF + kB);
                ldm4(bh[0], bbase + kB);
                ldm4(bh[1], bbase + 16 * XP + kB);
                ldm4(bl[0], bbase + WHALF + kB);
                ldm4(bl[1], bbase + WHALF + 16 * XP + kB);
#pragma unroll
                for (int ntq = 0; ntq < 2; ntq++) {
#pragma unroll
                    for (int sub = 0; sub < 2; sub++) {
                        int nt = ntq * 2 + sub;
                        uint32_t b0h = bh[ntq][sub * 2], b1h = bh[ntq][sub * 2 + 1];
                        uint32_t b0l = bl[ntq][sub * 2], b1l = bl[ntq][sub * 2 + 1];
                        mma16816(acc[nt], ah[0], ah[1], ah[2], ah[3], b0h, b1h);
                        mma16816(acc[nt], al[0], al[1], al[2], al[3], b0h, b1h);
                        mma16816(acc[nt], ah[0], ah[1], ah[2], ah[3], b0l, b1l);
                    }
                }
            }
        }
    }

    // epilogue: write 18 real outputs
    int px0 = wm * 16 + (lane >> 2);
    int nbase = y * Ww;
#pragma unroll
    for (int nt = 0; nt < 4; nt++) {
        int col = nt * 8 + (lane & 3) * 2;
        if (col < OCH) {
            float b0 = offset_b[col], b1 = offset_b[col + 1];
            g_off[img][nbase + px0][col]     = acc[nt][0] + b0;
            g_off[img][nbase + px0][col + 1] = acc[nt][1] + b1;
            g_off[img][nbase + px0 + 8][col]     = acc[nt][2] + b0;
            g_off[img][nbase + px0 + 8][col + 1] = acc[nt][3] + b1;
        }
    }
}

// ------------------------------ K3: deformable conv via mma.sync fp16x3 ------
#define PA 68                       // u32 row pitch (272 bytes)
#define MATB (128 * PA * 4)         // 34816 bytes (B half-matrix)
#define MATA (64 * PA * 4)          // 17408 bytes (A half-matrix)
#define OFF_ALO  MATA
#define OFF_BHI  (2 * MATA)
#define OFF_BLO  (2 * MATA + MATB)
#define OFF_OFS  (2 * MATA + 2 * MATB)          // int4[64]
#define OFF_WTS  (2 * MATA + 2 * MATB + 1024)   // float4[64]
#define K3_DYN   (2 * MATA + 2 * MATB + 2048)   // 106496

__device__ __forceinline__ void prefetch_B(uint32_t sb, int kk, int t) {
    uint32_t base = sb + OFF_BHI;
#pragma unroll
    for (int j = 0; j < 16; j++) {
        int chunk = t + 256 * j;              // 0..4095
        int lo = chunk >> 11;                 // 0: hi, 1: lo (2048 each: exact)
        int cc = chunk & 2047;
        int row = cc >> 4, ch16 = cc & 15;
        const __half* gsrc = lo ? &g_Wl[kk][row][ch16 * 8] : &g_Wh[kk][row][ch16 * 8];
        cp16(base + lo * MATB + (row * PA + ch16 * 4) * 4, gsrc);
    }
    asm volatile("cp.async.commit_group;" ::: "memory");
}

__global__ void __launch_bounds__(256, 2) k3_deform(const float* __restrict__ dcn_b) {
    extern __shared__ char B[];
    uint32_t sb = smem_u32(B);
    uint32_t* A32h = (uint32_t*)B;
    uint32_t* A32l = (uint32_t*)(B + OFF_ALO);
    int4*   s_ofs = (int4*)(B + OFF_OFS);
    float4* s_w   = (float4*)(B + OFF_WTS);

    int t = threadIdx.x, lane = t & 31, wid = t >> 5;
    int img = blockIdx.y, n0 = blockIdx.x * 64;
    const float* X = &g_xnhwc[img][0][0];

    float acc[8][4];
#pragma unroll
    for (int nt = 0; nt < 8; nt++)
#pragma unroll
        for (int f = 0; f < 4; f++) acc[nt][f] = 0.f;

    int cq = t & 31, pxg = t >> 5;
    int c = cq * 4;
    int wm = wid & 3, wn = wid >> 2;

    uint32_t arow = (lane & 7) + ((lane >> 3) & 1) * 8;
    uint32_t acolB = ((lane >> 4) & 1) * 16;
    uint32_t aAddr0 = sb + (wm * 16 + arow) * 272 + acolB;
    uint32_t brow = (lane & 7) + ((lane >> 4) & 1) * 8;
    uint32_t bcolB = ((lane >> 3) & 1) * 16;
    uint32_t bOff = (wn * 64 + brow) * 272 + bcolB;

    for (int kk = 0; kk < KK9; kk++) {
        __syncthreads();
        prefetch_B(sb, kk, t);

        if (t < 64) {
            int n = n0 + t;
            float dy = g_off[img][n][kk * 2 + 0];
            float dx = g_off[img][n][kk * 2 + 1];
            float py  = (float)((n >> 7) + kk / 3 - 1) + dy;
            float pxf = (float)((n & 127) + kk % 3 - 1) + dx;
            float y0f = floorf(py), x0f = floorf(pxf);
            int y0 = (int)y0f, x0 = (int)x0f;
            float wy = py - y0f, wx = pxf - x0f;
            int y1 = y0 + 1, x1 = x0 + 1;
            bool vy0 = (unsigned)y0 < (unsigned)Hh, vy1 = (unsigned)y1 < (unsigned)Hh;
            bool vx0 = (unsigned)x0 < (unsigned)Ww, vx1 = (unsigned)x1 < (unsigned)Ww;
            int yc0 = min(max(y0, 0), Hh - 1), yc1 = min(max(y1, 0), Hh - 1);
            int xc0 = min(max(x0, 0), Ww - 1), xc1 = min(max(x1, 0), Ww - 1);
            s_ofs[t] = make_int4((yc0 * Ww + xc0) * Cc, (yc0 * Ww + xc1) * Cc,
                                 (yc1 * Ww + xc0) * Cc, (yc1 * Ww + xc1) * Cc);
            s_w[t] = make_float4(vy0 && vx0 ? (1.f - wy) * (1.f - wx) : 0.f,
                                 vy0 && vx1 ? (1.f - wy) * wx : 0.f,
                                 vy1 && vx0 ? wy * (1.f - wx) : 0.f,
                                 vy1 && vx1 ? wy * wx : 0.f);
        }
        __syncthreads();

#pragma unroll 4
        for (int i = 0; i < 8; i++) {
            int px = pxg + i * 8;
            int4  o = s_ofs[px];
            float4 w = s_w[px];
            float4 v0 = *(const float4*)(X + o.x + c);
            float4 v1 = *(const float4*)(X + o.y + c);
            float4 v2 = *(const float4*)(X + o.z + c);
            float4 v3 = *(const float4*)(X + o.w + c);
            float s0 = w.x * v0.x + w.y * v1.x + w.z * v2.x + w.w * v3.x;
            float s1 = w.x * v0.y + w.y * v1.y + w.z * v2.y + w.w * v3.y;
            float s2 = w.x * v0.z + w.y * v1.z + w.z * v2.z + w.w * v3.z;
            float s3 = w.x * v0.w + w.y * v1.w + w.z * v2.w + w.w * v3.w;
            half2 h01 = __floats2half2_rn(s0, s1);
            half2 h23 = __floats2half2_rn(s2, s3);
            float2 f01 = __half22float2(h01), f23 = __half22float2(h23);
            half2 l01 = __floats2half2_rn(s0 - f01.x, s1 - f01.y);
            half2 l23 = __floats2half2_rn(s2 - f23.x, s3 - f23.y);
            *(uint2*)&A32h[px * PA + cq * 2] =
                make_uint2(*(uint32_t*)&h01, *(uint32_t*)&h23);
            *(uint2*)&A32l[px * PA + cq * 2] =
                make_uint2(*(uint32_t*)&l01, *(uint32_t*)&l23);
        }
        asm volatile("cp.async.wait_group 0;" ::: "memory");
        __syncthreads();

        uint32_t bh_base = sb + OFF_BHI + bOff;
        uint32_t bl_base = sb + OFF_BLO + bOff;

#pragma unroll
        for (int kt = 0; kt < 8; kt++) {
            uint32_t kB = kt * 32;
            uint32_t ah[4], al[4], bh[4][4], bl[4][4];
            ldm4(ah, aAddr0 + kB);
            ldm4(al, aAddr0 + OFF_ALO + kB);
#pragma unroll
            for (int ntq = 0; ntq < 4; ntq++) {
                ldm4(bh[ntq], bh_base + ntq * 16 * 272 + kB);
                ldm4(bl[ntq], bl_base + ntq * 16 * 272 + kB);
            }
#pragma unroll
            for (int ntq = 0; ntq < 4; ntq++) {
#pragma unroll
                for (int sub = 0; sub < 2; sub++) {
                    int nt = ntq * 2 + sub;
                    uint32_t b0h = bh[ntq][sub * 2], b1h = bh[ntq][sub * 2 + 1];
                    uint32_t b0l = bl[ntq][sub * 2], b1l = bl[ntq][sub * 2 + 1];
                    mma16816(acc[nt], ah[0], ah[1], ah[2], ah[3], b0h, b1h);
                    mma16816(acc[nt], al[0], al[1], al[2], al[3], b0h, b1h);
                    mma16816(acc[nt], ah[0], ah[1], ah[2], ah[3], b0l, b1l);
                }
            }
        }
    }

    int r0 = wm * 16 + (lane >> 2);
#pragma unroll
    for (int nt = 0; nt < 8; nt++) {
        int col = wn * 64 + nt * 8 + (lane & 3) * 2;
        float2 bias = *(const float2*)(dcn_b + col);
        float2 o0 = make_float2(acc[nt][0] + bias.x, acc[nt][1] + bias.y);
        float2 o1 = make_float2(acc[nt][2] + bias.x, acc[nt][3] + bias.y);
        *(float2*)&g_xd[img][n0 + r0][col] = o0;
        *(float2*)&g_xd[img][n0 + r0 + 8][col] = o1;
    }
}

// ------------------------------ K4: Gram partials G = Ud^T Vd ----------------
__global__ void k4_gpart() {
    __shared__ float Us[32][129];
    __shared__ float Vs[32][129];
    int b = blockIdx.y, chunk = blockIdx.x;
    int n0 = chunk * 128, t = threadIdx.x;
    int il = t & 15, jl = t >> 4;

    float acc[8][8];
#pragma unroll
    for (int ii = 0; ii < 8; ii++)
#pragma unroll
        for (int jj = 0; jj < 8; jj++) acc[ii][jj] = 0.f;
    float colsum = 0.f;

    for (int s = 0; s < 4; s++) {
        __syncthreads();
        for (int idx = t; idx < 32 * 128; idx += 256) {
            int cc = idx & 127, nl = idx >> 7;
            Us[nl][cc] = g_xd[b][n0 + s * 32 + nl][cc];
            Vs[nl][cc] = g_xd[2 + b][n0 + s * 32 + nl][cc];
        }
        __syncthreads();
#pragma unroll 4
        for (int nl = 0; nl < 32; nl++) {
            float av[8], bv[8];
#pragma unroll
            for (int ii = 0; ii < 8; ii++) av[ii] = Us[nl][il + 16 * ii];
#pragma unroll
            for (int jj = 0; jj < 8; jj++) bv[jj] = Vs[nl][jl + 16 * jj];
#pragma unroll
            for (int ii = 0; ii < 8; ii++)
#pragma unroll
                for (int jj = 0; jj < 8; jj++) acc[ii][jj] += av[ii] * bv[jj];
        }
        if (t < 128) {
            for (int nl = 0; nl < 32; nl++) colsum += Us[nl][t];
        } else {
            int cc = t - 128;
            for (int nl = 0; nl < 32; nl++) colsum += Vs[nl][cc];
        }
    }
    if (t < 128) g_sup[b][chunk][t] = colsum;
    else         g_svp[b][chunk][t - 128] = colsum;

    for (int g = 0; g < 4; g++) {
        __syncthreads();
#pragma unroll
        for (int jj = 0; jj < 8; jj++) {
            Us[il][jl + 16 * jj]      = acc[2 * g][jj];
            Us[16 + il][jl + 16 * jj] = acc[2 * g + 1][jj];
        }
        __syncthreads();
        for (int idx = t; idx < 32 * 128; idx += 256) {
            int j = idx & 127, r = idx >> 7;
            g_Gp[b][chunk][(32 * g + r) * 128 + j] = Us[r][j];
        }
    }
}

// ------------------------------ K4b: reduce partials -------------------------
__global__ void k4b_reduce() {
    int idx = blockIdx.x * 256 + threadIdx.x;
    if (idx < Bb * Cc * Cc) {
        int b = idx >> 14;
        int rem = idx & (Cc * Cc - 1);
        float s = 0.f;
        for (int ch = 0; ch < NCHUNK; ch++) s += g_Gp[b][ch][rem];
        g_G[b][rem] = s;
    } else {
        int k = idx - Bb * Cc * Cc;
        if (k < 2 * Bb * Cc) {
            int sel = k >> 8;
            int b = (k >> 7) & 1;
            int c = k & 127;
            float s = 0.f;
            if (sel) { for (int ch = 0; ch < NCHUNK; ch++) s += g_svp[b][ch][c]; g_sv[b][c] = s; }
            else     { for (int ch = 0; ch < NCHUNK; ch++) s += g_sup[b][ch][c]; g_su[b][c] = s; }
        }
    }
}

// ------------------------------ K5: tiny attention math ----------------------
__global__ void k5_attn(const float* __restrict__ q_w, const float* __restrict__ q_b,
                        const float* __restrict__ k_w, const float* __restrict__ k_b,
                        const float* __restrict__ v_w, const float* __restrict__ v_b) {
    __shared__ float P[4][128];
    __shared__ float L[4][128];
    __shared__ float ksv[128];
    __shared__ float qsu[4];
    int b = blockIdx.y;
    int i0 = blockIdx.x * 4;
    int t = threadIdx.x;
    int lane = t & 31, wid = t >> 5;

    if (t < 128) {
        float s = 0.f;
        for (int a = 0; a < 128; a++) s += k_w[t * 128 + a] * g_sv[b][a];
        ksv[t] = s;
    } else if (t < 132) {
        int i = i0 + (t - 128);
        float s = 0.f;
        for (int a = 0; a < 128; a++) s += q_w[i * 128 + a] * g_su[b][a];
        qsu[t - 128] = s;
    }
    __syncthreads();

    for (int idx = t; idx < 4 * 128; idx += 256) {
        int a = idx & 127, ii = idx >> 7;
        int i = i0 + ii;
        float s = 0.f;
        for (int m = 0; m < 128; m++) s += q_w[i * 128 + m] * g_G[b][m * 128 + a];
        P[ii][a] = s;
    }
    __syncthreads();

    const float scale = 0.088388347648318447f; // 128^-0.5
    for (int idx = t; idx < 4 * 128; idx += 256) {
        int j = idx & 127, ii = idx >> 7;
        int i = i0 + ii;
        float s = 0.f;
        for (int a = 0; a < 128; a++) s += P[ii][a] * k_w[j * 128 + a];
        s += qsu[ii] * k_b[j] + q_b[i] * ksv[j] + (float)Nn * q_b[i] * k_b[j];
        L[ii][j] = s * scale;
    }
    __syncthreads();

    if (wid < 4) {
        int r = wid;
        float v[4];
        float m = -1e30f;
#pragma unroll
        for (int q = 0; q < 4; q++) { v[q] = L[r][lane + 32 * q]; m = fmaxf(m, v[q]); }
#pragma unroll
        for (int o = 16; o > 0; o >>= 1) m = fmaxf(m, __shfl_xor_sync(0xFFFFFFFFu, m, o));
        float s = 0.f;
#pragma unroll
        for (int q = 0; q < 4; q++) { v[q] = expf(v[q] - m); s += v[q]; }
#pragma unroll
        for (int o = 16; o > 0; o >>= 1) s += __shfl_xor_sync(0xFFFFFFFFu, s, o);
        float inv = 1.f / s;
#pragma unroll
        for (int q = 0; q < 4; q++) L[r][lane + 32 * q] = v[q] * inv;
    }
    __syncthreads();

    for (int idx = t; idx < 4 * 128; idx += 256) {
        int m = idx & 127, ii = idx >> 7;
        float s = 0.f;
        for (int j = 0; j < 128; j++) s += L[ii][j] * v_w[j * 128 + m];
        g_Mt[b][m * 128 + (i0 + ii)] = s;
    }
    if (t < 4) {
        float s = 0.f;
        for (int j = 0; j < 128; j++) s += L[t][j] * v_b[j];
        g_r[b][i0 + t] = s;
    }
}

// ------------------------------ K6: out = M @ Vd^T + r -----------------------
__global__ void k6_out(float* __restrict__ out) {
    __shared__ float Ms[32][129];
    __shared__ float Vs[32][129];
    int b = blockIdx.y, n0 = blockIdx.x * 128, t = threadIdx.x;
    int il = t & 15, jl = t >> 4;

    float acc[8][8];
#pragma unroll
    for (int ii = 0; ii < 8; ii++)
#pragma unroll
        for (int jj = 0; jj < 8; jj++) acc[ii][jj] = 0.f;

    for (int s = 0; s < 4; s++) {
        __syncthreads();
        for (int idx = t; idx < 32 * 128; idx += 256) {
            int i = idx & 127, mm = idx >> 7;
            Ms[mm][i] = g_Mt[b][(s * 32 + mm) * 128 + i];
        }
        for (int idx = t; idx < 32 * 128; idx += 256) {
            int mmr = idx & 31, nl = idx >> 5;
            Vs[mmr][nl] = g_xd[2 + b][n0 + nl][s * 32 + mmr];
        }
        __syncthreads();
#pragma unroll 4
        for (int mm = 0; mm < 32; mm++) {
            float av[8], bv[8];
#pragma unroll
            for (int ii = 0; ii < 8; ii++) av[ii] = Ms[mm][il + 16 * ii];
#pragma unroll
            for (int jj = 0; jj < 8; jj++) bv[jj] = Vs[mm][jl + 16 * jj];
#pragma unroll
            for (int ii = 0; ii < 8; ii++)
#pragma unroll
                for (int jj = 0; jj < 8; jj++) acc[ii][jj] += av[ii] * bv[jj];
        }
    }

    for (int g = 0; g < 4; g++) {
        __syncthreads();
#pragma unroll
        for (int jj = 0; jj < 8; jj++) {
            Ms[il][jl + 16 * jj]      = acc[2 * g][jj];
            Ms[16 + il][jl + 16 * jj] = acc[2 * g + 1][jj];
        }
        __syncthreads();
        for (int idx = t; idx < 32 * 128; idx += 256) {
            int j = idx & 127, r = idx >> 7;
            int i = 32 * g + r;
            out[(size_t)(b * Cc + i) * Nn + n0 + j] = Ms[r][j] + g_r[b][i];
        }
    }
}

// ------------------------------ launch ---------------------------------------
extern "C" void kernel_launch(void* const* d_in, const int* in_sizes, int n_in,
                              void* d_out, int out_size) {
    (void)in_sizes; (void)n_in; (void)out_size;
    const float* u        = (const float*)d_in[0];
    const float* v        = (const float*)d_in[1];
    const float* offset_w = (const float*)d_in[2];
    const float* offset_b = (const float*)d_in[3];
    const float* dcn_w    = (const float*)d_in[4];
    const float* dcn_b    = (const float*)d_in[5];
    const float* q_w      = (const float*)d_in[6];
    const float* q_b      = (const float*)d_in[7];
    const float* k_w      = (const float*)d_in[8];
    const float* k_b      = (const float*)d_in[9];
    const float* v_w      = (const float*)d_in[10];
    const float* v_b      = (const float*)d_in[11];
    float* out = (float*)d_out;

    cudaFuncSetAttribute(k1_offset, cudaFuncAttributeMaxDynamicSharedMemorySize, K1_DYN);
    cudaFuncSetAttribute(k3_deform, cudaFuncAttributeMaxDynamicSharedMemorySize, K3_DYN);

    k0_prep<<<(KK9 * Cc * Cc + 255) / 256, 256>>>(dcn_w, offset_w);
    k2_transpose<<<dim3(Nn / 32, Cc / 32, NIMG), dim3(32, 8)>>>(u, v);
    k1_offset<<<dim3(Hh, NIMG), 256, K1_DYN>>>(offset_b);
    k3_deform<<<dim3(Nn / 64, NIMG), 256, K3_DYN>>>(dcn_b);
    k4_gpart<<<dim3(NCHUNK, Bb), 256>>>();
    k4b_reduce<<<130, 256>>>();
    k5_attn<<<dim3(32, Bb), 256>>>(q_w, q_b, k_w, k_b, v_w, v_b);
    k6_out<<<dim3(Nn / 128, Bb), 256>>>(out);
}